// round 3
// baseline (speedup 1.0000x reference)
#include <cuda_runtime.h>
#include <cuda_bf16.h>
#include <math.h>

// Problem constants
#define BB 4
#define SS 2048
#define DD 512
#define HH 8
#define KK 64
#define FF 64
#define MT (BB*SS)          // 8192 rows
#define EPS 1e-5f

// -------- scratch (no allocation allowed) --------
__device__ float g_q  [MT*DD];
__device__ float g_k  [MT*DD];
__device__ float g_v  [MT*DD];
__device__ float g_ctx[MT*DD];
__device__ float g_tmp[MT*DD];
__device__ float g_h  [MT*DD];
__device__ float g_hh [MT*FF];

// ======================================================================
// Tiled SGEMM with bias: C[M,N] = A[M,Kd] @ W[Kd,N] + bias
// BM=BN=64, BK=16, 256 threads, 4x4 register blocking.
// Requires M%64==0, N%64==0, Kd%16==0 (true for all our calls).
// ======================================================================
__global__ void sgemm_bias(const float* __restrict__ A,
                           const float* __restrict__ W,
                           const float* __restrict__ bias,
                           float* __restrict__ C,
                           int M, int N, int Kd) {
    __shared__ __align__(16) float As[16][64];
    __shared__ __align__(16) float Bs[16][64];

    const int tid = threadIdx.x;
    const int tr  = tid >> 4;      // 0..15
    const int tc  = tid & 15;      // 0..15
    const int m0  = blockIdx.y * 64;
    const int n0  = blockIdx.x * 64;

    float acc[4][4];
    #pragma unroll
    for (int i = 0; i < 4; i++)
        #pragma unroll
        for (int j = 0; j < 4; j++) acc[i][j] = 0.f;

    for (int kt = 0; kt < Kd; kt += 16) {
        #pragma unroll
        for (int i = 0; i < 4; i++) {
            int t = tid + i * 256;
            int m = t >> 4, k = t & 15;
            As[k][m] = A[(size_t)(m0 + m) * Kd + kt + k];
        }
        #pragma unroll
        for (int i = 0; i < 4; i++) {
            int t = tid + i * 256;
            int k = t >> 6, n = t & 63;
            Bs[k][n] = W[(size_t)(kt + k) * N + n0 + n];
        }
        __syncthreads();
        #pragma unroll
        for (int k = 0; k < 16; k++) {
            float4 a = *(const float4*)&As[k][tr * 4];
            float4 b = *(const float4*)&Bs[k][tc * 4];
            float av[4] = {a.x, a.y, a.z, a.w};
            float bv[4] = {b.x, b.y, b.z, b.w};
            #pragma unroll
            for (int i = 0; i < 4; i++)
                #pragma unroll
                for (int j = 0; j < 4; j++)
                    acc[i][j] = fmaf(av[i], bv[j], acc[i][j]);
        }
        __syncthreads();
    }

    #pragma unroll
    for (int i = 0; i < 4; i++) {
        int m = m0 + tr * 4 + i;
        #pragma unroll
        for (int j = 0; j < 4; j++) {
            int n = n0 + tc * 4 + j;
            C[(size_t)m * N + n] = acc[i][j] + bias[n];
        }
    }
}

// ======================================================================
// Fused attention: per block = one (b,h) and 16 query rows.
//  - computes scores (q.k^T / 8) into smem [16][2048]
//  - exact softmax (max-subtracted) in smem
//  - writes attention probs to output (if requested)
//  - accumulates ctx = probs @ v
// dynamic smem: q_s[16*64] | sc[16*2048] | kv[64*65]
// ======================================================================
#define QT 16
#define KT 64
#define KV_STRIDE 65
#define ATTN_SMEM_BYTES ((QT*KK + QT*SS + KT*KV_STRIDE) * 4)

__global__ void attn_kernel(const float* __restrict__ q,
                            const float* __restrict__ k,
                            const float* __restrict__ v,
                            float* __restrict__ atn,   // may be null
                            float* __restrict__ ctx) {
    extern __shared__ float sm[];
    float* q_s = sm;                       // 16*64
    float* sc  = sm + QT * KK;             // 16*2048
    float* kv  = sm + QT * KK + QT * SS;   // 64*65

    const int tid = threadIdx.x;           // 256 threads
    const int bh  = blockIdx.x;
    const int b   = bh / HH;
    const int h   = bh % HH;
    const int q0  = blockIdx.y * QT;

    // load q tile [16][64]
    #pragma unroll
    for (int i = 0; i < 4; i++) {
        int t  = tid + i * 256;
        int qi = t >> 6, d = t & 63;
        q_s[t] = q[(size_t)(b * SS + q0 + qi) * DD + h * KK + d];
    }

    // ---------- scores ----------
    const int qp = (tid >> 5) * 2;     // query pair base (0,2,..14)
    const int kp = (tid & 31) * 2;     // key pair base within chunk (0..62)
    const float inv_scale = 0.125f;    // 1/sqrt(D/H) = 1/8

    for (int c = 0; c < SS; c += KT) {
        __syncthreads();
        #pragma unroll
        for (int i = 0; i < 16; i++) {
            int t  = tid + i * 256;
            int kj = t >> 6, d = t & 63;
            kv[kj * KV_STRIDE + d] =
                k[(size_t)(b * SS + c + kj) * DD + h * KK + d];
        }
        __syncthreads();

        float s00 = 0.f, s01 = 0.f, s10 = 0.f, s11 = 0.f;
        #pragma unroll
        for (int d = 0; d < KK; d++) {
            float a0 = q_s[qp * KK + d];
            float a1 = q_s[(qp + 1) * KK + d];
            float b0 = kv[kp * KV_STRIDE + d];
            float b1 = kv[(kp + 1) * KV_STRIDE + d];
            s00 = fmaf(a0, b0, s00);
            s01 = fmaf(a0, b1, s01);
            s10 = fmaf(a1, b0, s10);
            s11 = fmaf(a1, b1, s11);
        }
        sc[qp * SS + c + kp]           = s00 * inv_scale;
        sc[qp * SS + c + kp + 1]       = s01 * inv_scale;
        sc[(qp + 1) * SS + c + kp]     = s10 * inv_scale;
        sc[(qp + 1) * SS + c + kp + 1] = s11 * inv_scale;
    }
    __syncthreads();

    // ---------- softmax: warp w handles rows 2w, 2w+1 ----------
    {
        const int w = tid >> 5, lane = tid & 31;
        #pragma unroll
        for (int rr = 0; rr < 2; rr++) {
            int r = w * 2 + rr;
            float mx = -1e30f;
            for (int j = lane; j < SS; j += 32)
                mx = fmaxf(mx, sc[r * SS + j]);
            #pragma unroll
            for (int o = 16; o; o >>= 1)
                mx = fmaxf(mx, __shfl_xor_sync(0xffffffff, mx, o));
            float sum = 0.f;
            for (int j = lane; j < SS; j += 32) {
                float e = __expf(sc[r * SS + j] - mx);
                sc[r * SS + j] = e;
                sum += e;
            }
            #pragma unroll
            for (int o = 16; o; o >>= 1)
                sum += __shfl_xor_sync(0xffffffff, sum, o);
            float inv = 1.f / sum;
            for (int j = lane; j < SS; j += 32)
                sc[r * SS + j] *= inv;
        }
    }
    __syncthreads();

    // ---------- write attention output ----------
    if (atn) {
        size_t base = ((size_t)(h * BB + b) * SS + q0) * SS;
        for (int idx = tid; idx < QT * SS; idx += 256) {
            int qi = idx >> 11, s = idx & (SS - 1);
            atn[base + (size_t)qi * SS + s] = sc[idx];
        }
    }

    // ---------- ctx = probs @ v ----------
    const int qi = tid >> 4;            // 0..15
    const int d0 = (tid & 15) * 4;      // 0..60
    float acc0 = 0.f, acc1 = 0.f, acc2 = 0.f, acc3 = 0.f;

    for (int c = 0; c < SS; c += KT) {
        __syncthreads();
        #pragma unroll
        for (int i = 0; i < 16; i++) {
            int t  = tid + i * 256;
            int s  = t >> 6, d = t & 63;
            kv[s * KK + d] = v[(size_t)(b * SS + c + s) * DD + h * KK + d];
        }
        __syncthreads();
        #pragma unroll 8
        for (int s = 0; s < KT; s++) {
            float p = sc[qi * SS + c + s];
            acc0 = fmaf(p, kv[s * KK + d0],     acc0);
            acc1 = fmaf(p, kv[s * KK + d0 + 1], acc1);
            acc2 = fmaf(p, kv[s * KK + d0 + 2], acc2);
            acc3 = fmaf(p, kv[s * KK + d0 + 3], acc3);
        }
    }

    size_t o = (size_t)(b * SS + q0 + qi) * DD + h * KK + d0;
    ctx[o]     = acc0;
    ctx[o + 1] = acc1;
    ctx[o + 2] = acc2;
    ctx[o + 3] = acc3;
}

// ======================================================================
// block reduce helper (256 threads)
// ======================================================================
__device__ __forceinline__ float blockReduceSum256(float v, float* red) {
    #pragma unroll
    for (int o = 16; o; o >>= 1) v += __shfl_xor_sync(0xffffffff, v, o);
    int w = threadIdx.x >> 5;
    if ((threadIdx.x & 31) == 0) red[w] = v;
    __syncthreads();
    float r = 0.f;
    if (threadIdx.x < 32) {
        r = (threadIdx.x < 8) ? red[threadIdx.x] : 0.f;
        #pragma unroll
        for (int o = 4; o; o >>= 1) r += __shfl_xor_sync(0xffffffff, r, o);
        if (threadIdx.x == 0) red[0] = r;
    }
    __syncthreads();
    float out = red[0];
    __syncthreads();
    return out;
}

// ======================================================================
// mha_out = LN(tmp + x) with (g_mha,b_mha); h = LN(mha_out + x) with (g_net1,b_net1)
// tmp already contains ctx@Wo + bo. One block per row, 256 threads (2 elems each).
// ======================================================================
__global__ void addln2_kernel(const float* __restrict__ tmp,
                              const float* __restrict__ x,
                              const float* __restrict__ gm, const float* __restrict__ bm,
                              const float* __restrict__ g1, const float* __restrict__ b1,
                              float* __restrict__ hout) {
    __shared__ float red[32];
    const int r = blockIdx.x;
    const int d0 = threadIdx.x, d1 = threadIdx.x + 256;
    size_t base = (size_t)r * DD;

    float x0 = x[base + d0], x1 = x[base + d1];
    float p0 = tmp[base + d0] + x0;
    float p1 = tmp[base + d1] + x1;

    float mean = blockReduceSum256(p0 + p1, red) * (1.f / DD);
    float dv0 = p0 - mean, dv1 = p1 - mean;
    float var = blockReduceSum256(dv0 * dv0 + dv1 * dv1, red) * (1.f / DD);
    float rstd = rsqrtf(var + EPS);

    float m0 = dv0 * rstd * gm[d0] + bm[d0];
    float m1 = dv1 * rstd * gm[d1] + bm[d1];

    float t0 = m0 + x0, t1 = m1 + x1;
    float mean2 = blockReduceSum256(t0 + t1, red) * (1.f / DD);
    float e0 = t0 - mean2, e1 = t1 - mean2;
    float var2 = blockReduceSum256(e0 * e0 + e1 * e1, red) * (1.f / DD);
    float rstd2 = rsqrtf(var2 + EPS);

    hout[base + d0] = e0 * rstd2 * g1[d0] + b1[d0];
    hout[base + d1] = e1 * rstd2 * g1[d1] + b1[d1];
}

// ======================================================================
// FFN part 1: hh = relu(h @ W1 + b1)   (4 rows per block, 256 threads)
// ======================================================================
__global__ void ffn1_kernel(const float* __restrict__ h,
                            const float* __restrict__ W1,
                            const float* __restrict__ b1,
                            float* __restrict__ hh) {
    __shared__ float hs[4 * DD];
    const int r0 = blockIdx.x * 4;
    const int tid = threadIdx.x;
    #pragma unroll
    for (int i = 0; i < 8; i++) {
        int t = tid + i * 256;
        hs[t] = h[(size_t)r0 * DD + t];
    }
    __syncthreads();
    const int rr = tid >> 6, n = tid & 63;
    float s = b1[n];
    #pragma unroll 4
    for (int k = 0; k < DD; k++)
        s = fmaf(hs[rr * DD + k], W1[k * FF + n], s);
    hh[(size_t)(r0 + rr) * FF + n] = fmaxf(s, 0.f);
}

// ======================================================================
// FFN part 2 + final LN: out = LN(hh @ W2 + b2 + h) with (g_net2,b_net2)
// One block per row, 256 threads (2 elems each).
// ======================================================================
__global__ void ffn2ln_kernel(const float* __restrict__ hh,
                              const float* __restrict__ W2,
                              const float* __restrict__ b2,
                              const float* __restrict__ h,
                              const float* __restrict__ g2, const float* __restrict__ bb2,
                              float* __restrict__ out) {
    __shared__ float hhs[FF];
    __shared__ float red[32];
    const int r = blockIdx.x;
    const int tid = threadIdx.x;
    if (tid < FF) hhs[tid] = hh[(size_t)r * FF + tid];
    __syncthreads();

    const int d0 = tid, d1 = tid + 256;
    size_t base = (size_t)r * DD;
    float v0 = b2[d0] + h[base + d0];
    float v1 = b2[d1] + h[base + d1];
    #pragma unroll
    for (int f = 0; f < FF; f++) {
        float hv = hhs[f];
        v0 = fmaf(hv, W2[f * DD + d0], v0);
        v1 = fmaf(hv, W2[f * DD + d1], v1);
    }

    float mean = blockReduceSum256(v0 + v1, red) * (1.f / DD);
    float e0 = v0 - mean, e1 = v1 - mean;
    float var = blockReduceSum256(e0 * e0 + e1 * e1, red) * (1.f / DD);
    float rstd = rsqrtf(var + EPS);

    out[base + d0] = e0 * rstd * g2[d0] + bb2[d0];
    out[base + d1] = e1 * rstd * g2[d1] + bb2[d1];
}

// ======================================================================
// launch
// ======================================================================
extern "C" void kernel_launch(void* const* d_in, const int* in_sizes, int n_in,
                              void* d_out, int out_size) {
    const float* x      = (const float*)d_in[0];
    const float* Wq     = (const float*)d_in[1];
    const float* bq     = (const float*)d_in[2];
    const float* Wk     = (const float*)d_in[3];
    const float* bk     = (const float*)d_in[4];
    const float* Wv     = (const float*)d_in[5];
    const float* bv     = (const float*)d_in[6];
    const float* Wo     = (const float*)d_in[7];
    const float* bo     = (const float*)d_in[8];
    const float* g_mha  = (const float*)d_in[9];
    const float* b_mha  = (const float*)d_in[10];
    const float* g_net1 = (const float*)d_in[11];
    const float* b_net1 = (const float*)d_in[12];
    const float* W1     = (const float*)d_in[13];
    const float* b1     = (const float*)d_in[14];
    const float* W2     = (const float*)d_in[15];
    const float* b2     = (const float*)d_in[16];
    const float* g_net2 = (const float*)d_in[17];
    const float* b_net2 = (const float*)d_in[18];

    float* qb;  cudaGetSymbolAddress((void**)&qb,  g_q);
    float* kb;  cudaGetSymbolAddress((void**)&kb,  g_k);
    float* vb;  cudaGetSymbolAddress((void**)&vb,  g_v);
    float* ctx; cudaGetSymbolAddress((void**)&ctx, g_ctx);
    float* tmp; cudaGetSymbolAddress((void**)&tmp, g_tmp);
    float* hb;  cudaGetSymbolAddress((void**)&hb,  g_h);
    float* hhb; cudaGetSymbolAddress((void**)&hhb, g_hh);

    const size_t OUT_ELEMS = (size_t)BB * SS * DD;
    float* outp = (float*)d_out;
    float* atnp = ((size_t)out_size > OUT_ELEMS) ? (float*)d_out + OUT_ELEMS : nullptr;

    cudaFuncSetAttribute(attn_kernel,
                         cudaFuncAttributeMaxDynamicSharedMemorySize,
                         ATTN_SMEM_BYTES);

    dim3 gproj(DD / 64, MT / 64);
    sgemm_bias<<<gproj, 256>>>(x, Wq, bq, qb, MT, DD, DD);
    sgemm_bias<<<gproj, 256>>>(x, Wk, bk, kb, MT, DD, DD);
    sgemm_bias<<<gproj, 256>>>(x, Wv, bv, vb, MT, DD, DD);

    dim3 gattn(BB * HH, SS / QT);
    attn_kernel<<<gattn, 256, ATTN_SMEM_BYTES>>>(qb, kb, vb, atnp, ctx);

    sgemm_bias<<<gproj, 256>>>(ctx, Wo, bo, tmp, MT, DD, DD);

    addln2_kernel<<<MT, 256>>>(tmp, x, g_mha, b_mha, g_net1, b_net1, hb);

    ffn1_kernel<<<MT / 4, 256>>>(hb, W1, b1, hhb);

    ffn2ln_kernel<<<MT, 256>>>(hhb, W2, b2, hb, g_net2, b_net2, outp);
}

// round 4
// speedup vs baseline: 1.6048x; 1.6048x over previous
#include <cuda_runtime.h>
#include <cuda_bf16.h>
#include <math.h>

// Problem constants
#define BB 4
#define SS 2048
#define DD 512
#define HH 8
#define KK 64
#define FF 64
#define MT (BB*SS)          // 8192 rows
#define EPS 1e-5f

// -------- scratch (no allocation allowed) --------
__device__ float g_q  [MT*DD];
__device__ float g_k  [MT*DD];
__device__ float g_v  [MT*DD];
__device__ float g_ctx[MT*DD];
__device__ float g_tmp[MT*DD];
__device__ float g_h  [MT*DD];
__device__ float g_hh [MT*FF];

// ======================================================================
// Classic SGEMM: C[M,N] = A[M,Kd] @ W[Kd,N] + bias
// BM=128, BN=128, BK=8, 256 threads, 8x8 register tile. 1B LDS / FMA.
// Requires M%128==0, N%128==0, Kd%8==0.
// ======================================================================
__global__ void __launch_bounds__(256)
sgemm_bias(const float* __restrict__ A,
           const float* __restrict__ W,
           const float* __restrict__ bias,
           float* __restrict__ C,
           int M, int N, int Kd) {
    __shared__ __align__(16) float As[8 * 128];   // transposed: As[k][m]
    __shared__ __align__(16) float Bs[8 * 128];   // Bs[k][n]

    const int tid  = threadIdx.x;
    const int m0   = blockIdx.y * 128;
    const int n0   = blockIdx.x * 128;
    const int arow = tid >> 1;            // 0..127
    const int ak4  = (tid & 1) * 4;       // 0 or 4
    const int brow = tid >> 5;            // 0..7
    const int bn4  = (tid & 31) * 4;      // 0..124
    const int tm   = tid >> 4;            // 0..15
    const int tn   = tid & 15;            // 0..15

    float acc[8][8];
    #pragma unroll
    for (int i = 0; i < 8; i++)
        #pragma unroll
        for (int j = 0; j < 8; j++) acc[i][j] = 0.f;

    for (int kt = 0; kt < Kd; kt += 8) {
        float4 av = *(const float4*)&A[(size_t)(m0 + arow) * Kd + kt + ak4];
        float4 bv = *(const float4*)&W[(size_t)(kt + brow) * N + n0 + bn4];
        __syncthreads();
        As[(ak4 + 0) * 128 + arow] = av.x;
        As[(ak4 + 1) * 128 + arow] = av.y;
        As[(ak4 + 2) * 128 + arow] = av.z;
        As[(ak4 + 3) * 128 + arow] = av.w;
        *(float4*)&Bs[brow * 128 + bn4] = bv;
        __syncthreads();

        #pragma unroll
        for (int kk = 0; kk < 8; kk++) {
            float rm[8], rn[8];
            *(float4*)&rm[0] = *(const float4*)&As[kk * 128 + tm * 8];
            *(float4*)&rm[4] = *(const float4*)&As[kk * 128 + tm * 8 + 4];
            *(float4*)&rn[0] = *(const float4*)&Bs[kk * 128 + tn * 8];
            *(float4*)&rn[4] = *(const float4*)&Bs[kk * 128 + tn * 8 + 4];
            #pragma unroll
            for (int i = 0; i < 8; i++)
                #pragma unroll
                for (int j = 0; j < 8; j++)
                    acc[i][j] = fmaf(rm[i], rn[j], acc[i][j]);
        }
    }

    float4 bv0 = *(const float4*)&bias[n0 + tn * 8];
    float4 bv1 = *(const float4*)&bias[n0 + tn * 8 + 4];
    #pragma unroll
    for (int i = 0; i < 8; i++) {
        size_t row = (size_t)(m0 + tm * 8 + i) * N + n0 + tn * 8;
        float4 o0 = {acc[i][0] + bv0.x, acc[i][1] + bv0.y,
                     acc[i][2] + bv0.z, acc[i][3] + bv0.w};
        float4 o1 = {acc[i][4] + bv1.x, acc[i][5] + bv1.y,
                     acc[i][6] + bv1.z, acc[i][7] + bv1.w};
        *(float4*)&C[row]     = o0;
        *(float4*)&C[row + 4] = o1;
    }
}

// ======================================================================
// score_softmax: per block = (b,h, 16 query rows).
// scores(16x2048) via 4x4 reg tiles (k chunk 256 transposed in smem),
// exact softmax, write normalized probs to atn (global).
// smem: sc[16*2048] | kts[64*260] | qs[64*20]
// ======================================================================
#define KTS_STRIDE 260
#define QS_STRIDE  20
#define SCORE_SMEM ((16*SS + 64*KTS_STRIDE + 64*QS_STRIDE) * 4)

__global__ void __launch_bounds__(256)
score_softmax(const float* __restrict__ q,
              const float* __restrict__ k,
              float* __restrict__ atn) {
    extern __shared__ float sm[];
    float* sc  = sm;                        // 16*2048
    float* kts = sm + 16 * SS;              // 64 x 260 (kts[d][kj])
    float* qs  = kts + 64 * KTS_STRIDE;     // 64 x 20  (qs[d][qi])

    const int tid = threadIdx.x;
    const int bh  = blockIdx.x;
    const int b   = bh >> 3;
    const int h   = bh & 7;
    const int q0  = blockIdx.y * 16;

    // load q tile transposed
    #pragma unroll
    for (int i = 0; i < 4; i++) {
        int idx = tid + i * 256;
        int d = idx & 63, qi = idx >> 6;
        qs[d * QS_STRIDE + qi] =
            q[(size_t)(b * SS + q0 + qi) * DD + h * KK + d];
    }

    const int qq = tid >> 6;    // 0..3
    const int kk = tid & 63;    // 0..63

    for (int c = 0; c < SS; c += 256) {
        __syncthreads();
        // load 256-key chunk transposed: kts[d][kj]
        #pragma unroll
        for (int i = 0; i < 16; i++) {
            int lin = tid + i * 256;
            int kj = lin >> 4, d4 = (lin & 15) * 4;
            float4 kv = *(const float4*)&k[(size_t)(b * SS + c + kj) * DD + h * KK + d4];
            kts[(d4 + 0) * KTS_STRIDE + kj] = kv.x;
            kts[(d4 + 1) * KTS_STRIDE + kj] = kv.y;
            kts[(d4 + 2) * KTS_STRIDE + kj] = kv.z;
            kts[(d4 + 3) * KTS_STRIDE + kj] = kv.w;
        }
        __syncthreads();

        float acc[4][4];
        #pragma unroll
        for (int i = 0; i < 4; i++)
            #pragma unroll
            for (int j = 0; j < 4; j++) acc[i][j] = 0.f;

        #pragma unroll 16
        for (int d = 0; d < 64; d++) {
            float4 qv = *(const float4*)&qs[d * QS_STRIDE + qq * 4];
            float4 kv = *(const float4*)&kts[d * KTS_STRIDE + kk * 4];
            float qa[4] = {qv.x, qv.y, qv.z, qv.w};
            float ka[4] = {kv.x, kv.y, kv.z, kv.w};
            #pragma unroll
            for (int i = 0; i < 4; i++)
                #pragma unroll
                for (int j = 0; j < 4; j++)
                    acc[i][j] = fmaf(qa[i], ka[j], acc[i][j]);
        }

        #pragma unroll
        for (int r = 0; r < 4; r++) {
            float4 o = {acc[r][0] * 0.125f, acc[r][1] * 0.125f,
                        acc[r][2] * 0.125f, acc[r][3] * 0.125f};
            *(float4*)&sc[(qq * 4 + r) * SS + c + kk * 4] = o;
        }
    }
    __syncthreads();

    // softmax + write: warp w handles rows 2w, 2w+1
    const int w = tid >> 5, lane = tid & 31;
    #pragma unroll
    for (int rr = 0; rr < 2; rr++) {
        int r = w * 2 + rr;
        float mx = -1e30f;
        for (int j = lane * 4; j < SS; j += 128) {
            float4 v = *(const float4*)&sc[r * SS + j];
            mx = fmaxf(mx, fmaxf(fmaxf(v.x, v.y), fmaxf(v.z, v.w)));
        }
        #pragma unroll
        for (int o = 16; o; o >>= 1)
            mx = fmaxf(mx, __shfl_xor_sync(0xffffffff, mx, o));

        float sum = 0.f;
        for (int j = lane * 4; j < SS; j += 128) {
            float4 v = *(const float4*)&sc[r * SS + j];
            v.x = __expf(v.x - mx); v.y = __expf(v.y - mx);
            v.z = __expf(v.z - mx); v.w = __expf(v.w - mx);
            *(float4*)&sc[r * SS + j] = v;
            sum += v.x + v.y + v.z + v.w;
        }
        #pragma unroll
        for (int o = 16; o; o >>= 1)
            sum += __shfl_xor_sync(0xffffffff, sum, o);
        float inv = 1.f / sum;

        size_t arow = ((size_t)(h * BB + b) * SS + q0 + r) * SS;
        for (int j = lane * 4; j < SS; j += 128) {
            float4 v = *(const float4*)&sc[r * SS + j];
            v.x *= inv; v.y *= inv; v.z *= inv; v.w *= inv;
            *(float4*)&atn[arow + j] = v;
        }
    }
}

// ======================================================================
// ctx_gemm: per (b,h): ctx[2048,64] = P[2048,2048] @ V[2048,64]
// BM=128 (q), BN=64 (d), BK=32 (s), 256 threads, 8x4 reg tile.
// P is read from atn output (global).
// ======================================================================
__global__ void __launch_bounds__(256)
ctx_gemm(const float* __restrict__ P,
         const float* __restrict__ v,
         float* __restrict__ ctx) {
    __shared__ __align__(16) float Ps[32 * 132];  // Ps[s][q]
    __shared__ __align__(16) float Vs[32 * 64];   // Vs[s][d]

    const int tid = threadIdx.x;
    const int bh  = blockIdx.x;
    const int b   = bh >> 3;
    const int h   = bh & 7;
    const int q0  = blockIdx.y * 128;
    const size_t pbase = (size_t)(h * BB + b) * SS * SS;

    const int tq = tid >> 4;   // 0..15 -> q rows tq*8..+7
    const int td = tid & 15;   // 0..15 -> d cols td*4..+3

    float acc[8][4];
    #pragma unroll
    for (int i = 0; i < 8; i++)
        #pragma unroll
        for (int j = 0; j < 4; j++) acc[i][j] = 0.f;

    for (int c = 0; c < SS; c += 32) {
        __syncthreads();
        #pragma unroll
        for (int i = 0; i < 4; i++) {
            int lin = tid + i * 256;
            int qr = lin >> 3, s4 = (lin & 7) * 4;
            float4 pv = *(const float4*)&P[pbase + (size_t)(q0 + qr) * SS + c + s4];
            Ps[(s4 + 0) * 132 + qr] = pv.x;
            Ps[(s4 + 1) * 132 + qr] = pv.y;
            Ps[(s4 + 2) * 132 + qr] = pv.z;
            Ps[(s4 + 3) * 132 + qr] = pv.w;
        }
        #pragma unroll
        for (int i = 0; i < 2; i++) {
            int lin = tid + i * 256;
            int s = lin >> 4, d4 = (lin & 15) * 4;
            *(float4*)&Vs[s * 64 + d4] =
                *(const float4*)&v[(size_t)(b * SS + c + s) * DD + h * KK + d4];
        }
        __syncthreads();

        #pragma unroll 8
        for (int s = 0; s < 32; s++) {
            float4 m0 = *(const float4*)&Ps[s * 132 + tq * 8];
            float4 m1 = *(const float4*)&Ps[s * 132 + tq * 8 + 4];
            float4 n0 = *(const float4*)&Vs[s * 64 + td * 4];
            float ma[8] = {m0.x, m0.y, m0.z, m0.w, m1.x, m1.y, m1.z, m1.w};
            float na[4] = {n0.x, n0.y, n0.z, n0.w};
            #pragma unroll
            for (int i = 0; i < 8; i++)
                #pragma unroll
                for (int j = 0; j < 4; j++)
                    acc[i][j] = fmaf(ma[i], na[j], acc[i][j]);
        }
    }

    #pragma unroll
    for (int i = 0; i < 8; i++) {
        float4 o = {acc[i][0], acc[i][1], acc[i][2], acc[i][3]};
        *(float4*)&ctx[(size_t)(b * SS + q0 + tq * 8 + i) * DD + h * KK + td * 4] = o;
    }
}

// ======================================================================
// FFN1 GEMM + ReLU: C[M,64] = relu(A[M,512] @ W[512,64] + bias)
// BM=128, BN=64, BK=32, 256 threads, 8x4 reg tile.
// ======================================================================
__global__ void __launch_bounds__(256)
ffn1_gemm(const float* __restrict__ A,
          const float* __restrict__ W,
          const float* __restrict__ bias,
          float* __restrict__ C) {
    __shared__ __align__(16) float As[32 * 132];  // As[k][m]
    __shared__ __align__(16) float Ws[32 * 64];   // Ws[k][n]

    const int tid = threadIdx.x;
    const int m0  = blockIdx.x * 128;
    const int tq = tid >> 4;
    const int td = tid & 15;

    float acc[8][4];
    #pragma unroll
    for (int i = 0; i < 8; i++)
        #pragma unroll
        for (int j = 0; j < 4; j++) acc[i][j] = 0.f;

    for (int c = 0; c < DD; c += 32) {
        __syncthreads();
        #pragma unroll
        for (int i = 0; i < 4; i++) {
            int lin = tid + i * 256;
            int qr = lin >> 3, k4 = (lin & 7) * 4;
            float4 av = *(const float4*)&A[(size_t)(m0 + qr) * DD + c + k4];
            As[(k4 + 0) * 132 + qr] = av.x;
            As[(k4 + 1) * 132 + qr] = av.y;
            As[(k4 + 2) * 132 + qr] = av.z;
            As[(k4 + 3) * 132 + qr] = av.w;
        }
        #pragma unroll
        for (int i = 0; i < 2; i++) {
            int lin = tid + i * 256;
            int kr = lin >> 4, n4 = (lin & 15) * 4;
            *(float4*)&Ws[kr * 64 + n4] = *(const float4*)&W[(size_t)(c + kr) * FF + n4];
        }
        __syncthreads();

        #pragma unroll 8
        for (int s = 0; s < 32; s++) {
            float4 m0v = *(const float4*)&As[s * 132 + tq * 8];
            float4 m1v = *(const float4*)&As[s * 132 + tq * 8 + 4];
            float4 n0v = *(const float4*)&Ws[s * 64 + td * 4];
            float ma[8] = {m0v.x, m0v.y, m0v.z, m0v.w, m1v.x, m1v.y, m1v.z, m1v.w};
            float na[4] = {n0v.x, n0v.y, n0v.z, n0v.w};
            #pragma unroll
            for (int i = 0; i < 8; i++)
                #pragma unroll
                for (int j = 0; j < 4; j++)
                    acc[i][j] = fmaf(ma[i], na[j], acc[i][j]);
        }
    }

    float4 bv = *(const float4*)&bias[td * 4];
    float ba[4] = {bv.x, bv.y, bv.z, bv.w};
    #pragma unroll
    for (int i = 0; i < 8; i++) {
        float4 o = {fmaxf(acc[i][0] + ba[0], 0.f), fmaxf(acc[i][1] + ba[1], 0.f),
                    fmaxf(acc[i][2] + ba[2], 0.f), fmaxf(acc[i][3] + ba[3], 0.f)};
        *(float4*)&C[(size_t)(m0 + tq * 8 + i) * FF + td * 4] = o;
    }
}

// ======================================================================
// block reduce helper (256 threads)
// ======================================================================
__device__ __forceinline__ float blockReduceSum256(float v, float* red) {
    #pragma unroll
    for (int o = 16; o; o >>= 1) v += __shfl_xor_sync(0xffffffff, v, o);
    int w = threadIdx.x >> 5;
    if ((threadIdx.x & 31) == 0) red[w] = v;
    __syncthreads();
    float r = 0.f;
    if (threadIdx.x < 32) {
        r = (threadIdx.x < 8) ? red[threadIdx.x] : 0.f;
        #pragma unroll
        for (int o = 4; o; o >>= 1) r += __shfl_xor_sync(0xffffffff, r, o);
        if (threadIdx.x == 0) red[0] = r;
    }
    __syncthreads();
    float out = red[0];
    __syncthreads();
    return out;
}

// ======================================================================
// mha_out = LN(tmp + x) (g_mha,b_mha); h = LN(mha_out + x) (g_net1,b_net1)
// ======================================================================
__global__ void addln2_kernel(const float* __restrict__ tmp,
                              const float* __restrict__ x,
                              const float* __restrict__ gm, const float* __restrict__ bm,
                              const float* __restrict__ g1, const float* __restrict__ b1,
                              float* __restrict__ hout) {
    __shared__ float red[32];
    const int r = blockIdx.x;
    const int d0 = threadIdx.x, d1 = threadIdx.x + 256;
    size_t base = (size_t)r * DD;

    float x0 = x[base + d0], x1 = x[base + d1];
    float p0 = tmp[base + d0] + x0;
    float p1 = tmp[base + d1] + x1;

    float mean = blockReduceSum256(p0 + p1, red) * (1.f / DD);
    float dv0 = p0 - mean, dv1 = p1 - mean;
    float var = blockReduceSum256(dv0 * dv0 + dv1 * dv1, red) * (1.f / DD);
    float rstd = rsqrtf(var + EPS);

    float m0 = dv0 * rstd * gm[d0] + bm[d0];
    float m1 = dv1 * rstd * gm[d1] + bm[d1];

    float t0 = m0 + x0, t1 = m1 + x1;
    float mean2 = blockReduceSum256(t0 + t1, red) * (1.f / DD);
    float e0 = t0 - mean2, e1 = t1 - mean2;
    float var2 = blockReduceSum256(e0 * e0 + e1 * e1, red) * (1.f / DD);
    float rstd2 = rsqrtf(var2 + EPS);

    hout[base + d0] = e0 * rstd2 * g1[d0] + b1[d0];
    hout[base + d1] = e1 * rstd2 * g1[d1] + b1[d1];
}

// ======================================================================
// out = LN(tmp + h) with (g,b). One block per row.
// ======================================================================
__global__ void addln1_kernel(const float* __restrict__ tmp,
                              const float* __restrict__ h,
                              const float* __restrict__ g, const float* __restrict__ b,
                              float* __restrict__ out) {
    __shared__ float red[32];
    const int r = blockIdx.x;
    const int d0 = threadIdx.x, d1 = threadIdx.x + 256;
    size_t base = (size_t)r * DD;

    float v0 = tmp[base + d0] + h[base + d0];
    float v1 = tmp[base + d1] + h[base + d1];

    float mean = blockReduceSum256(v0 + v1, red) * (1.f / DD);
    float e0 = v0 - mean, e1 = v1 - mean;
    float var = blockReduceSum256(e0 * e0 + e1 * e1, red) * (1.f / DD);
    float rstd = rsqrtf(var + EPS);

    out[base + d0] = e0 * rstd * g[d0] + b[d0];
    out[base + d1] = e1 * rstd * g[d1] + b[d1];
}

// ======================================================================
// launch
// ======================================================================
extern "C" void kernel_launch(void* const* d_in, const int* in_sizes, int n_in,
                              void* d_out, int out_size) {
    const float* x      = (const float*)d_in[0];
    const float* Wq     = (const float*)d_in[1];
    const float* bq     = (const float*)d_in[2];
    const float* Wk     = (const float*)d_in[3];
    const float* bk     = (const float*)d_in[4];
    const float* Wv     = (const float*)d_in[5];
    const float* bv     = (const float*)d_in[6];
    const float* Wo     = (const float*)d_in[7];
    const float* bo     = (const float*)d_in[8];
    const float* g_mha  = (const float*)d_in[9];
    const float* b_mha  = (const float*)d_in[10];
    const float* g_net1 = (const float*)d_in[11];
    const float* b_net1 = (const float*)d_in[12];
    const float* W1     = (const float*)d_in[13];
    const float* b1     = (const float*)d_in[14];
    const float* W2     = (const float*)d_in[15];
    const float* b2     = (const float*)d_in[16];
    const float* g_net2 = (const float*)d_in[17];
    const float* b_net2 = (const float*)d_in[18];

    float* qb;  cudaGetSymbolAddress((void**)&qb,  g_q);
    float* kb;  cudaGetSymbolAddress((void**)&kb,  g_k);
    float* vb;  cudaGetSymbolAddress((void**)&vb,  g_v);
    float* ctx; cudaGetSymbolAddress((void**)&ctx, g_ctx);
    float* tmp; cudaGetSymbolAddress((void**)&tmp, g_tmp);
    float* hb;  cudaGetSymbolAddress((void**)&hb,  g_h);
    float* hhb; cudaGetSymbolAddress((void**)&hhb, g_hh);

    const size_t OUT_ELEMS = (size_t)BB * SS * DD;
    float* outp = (float*)d_out;
    float* atnp = (float*)d_out + OUT_ELEMS;   // probs live in the output buffer

    cudaFuncSetAttribute(score_softmax,
                         cudaFuncAttributeMaxDynamicSharedMemorySize,
                         SCORE_SMEM);

    dim3 gproj(DD / 128, MT / 128);            // 4 x 64
    sgemm_bias<<<gproj, 256>>>(x, Wq, bq, qb, MT, DD, DD);
    sgemm_bias<<<gproj, 256>>>(x, Wk, bk, kb, MT, DD, DD);
    sgemm_bias<<<gproj, 256>>>(x, Wv, bv, vb, MT, DD, DD);

    dim3 gscore(BB * HH, SS / 16);             // 32 x 128
    score_softmax<<<gscore, 256, SCORE_SMEM>>>(qb, kb, atnp);

    dim3 gctx(BB * HH, SS / 128);              // 32 x 16
    ctx_gemm<<<gctx, 256>>>(atnp, vb, ctx);

    sgemm_bias<<<gproj, 256>>>(ctx, Wo, bo, tmp, MT, DD, DD);

    addln2_kernel<<<MT, 256>>>(tmp, x, g_mha, b_mha, g_net1, b_net1, hb);

    ffn1_gemm<<<MT / 128, 256>>>(hb, W1, b1, hhb);

    sgemm_bias<<<gproj, 256>>>(hhb, W2, b2, tmp, MT, DD, FF);

    addln1_kernel<<<MT, 256>>>(tmp, hb, g_net2, b_net2, outp);
}

// round 5
// speedup vs baseline: 2.0757x; 1.2935x over previous
#include <cuda_runtime.h>
#include <cuda_bf16.h>
#include <math.h>

// Problem constants
#define BB 4
#define SS 2048
#define DD 512
#define HH 8
#define KK 64
#define FF 64
#define MT (BB*SS)          // 8192 rows
#define EPS 1e-5f

// -------- scratch (no allocation allowed) --------
__device__ float g_q  [MT*DD];
__device__ float g_k  [MT*DD];
__device__ float g_v  [MT*DD];
__device__ float g_ctx[MT*DD];
__device__ float g_tmp[MT*DD];
__device__ float g_h  [MT*DD];
__device__ float g_hh [MT*FF];

// ======================================================================
// fast exp on FMA/ALU pipes only (no MUFU). |rel err| ~ 5e-6 for x<=0.
// ======================================================================
__device__ __forceinline__ float fast_exp(float x) {
    x = fmaxf(x, -87.0f);
    float y0 = x * 1.4426950408889634f;     // x * log2(e)
    float z  = y0 + 12582912.0f;            // round-to-nearest via magic
    float t  = z - 12582912.0f;
    float f  = y0 - t;                      // f in [-0.5, 0.5]
    int   n  = __float_as_int(z) - 0x4B400000;
    float p  = 0.0013333558f;
    p = fmaf(p, f, 0.0096181291f);
    p = fmaf(p, f, 0.0555041087f);
    p = fmaf(p, f, 0.2402265069f);
    p = fmaf(p, f, 0.6931471806f);
    p = fmaf(p, f, 1.0f);
    return p * __int_as_float((n + 127) << 23);
}

// ======================================================================
// Classic SGEMM: C[M,N] = A[M,Kd] @ W[Kd,N] + bias
// BM=128, BN=128, BK=8, 256 threads, 8x8 register tile.
// ======================================================================
__global__ void __launch_bounds__(256)
sgemm_bias(const float* __restrict__ A,
           const float* __restrict__ W,
           const float* __restrict__ bias,
           float* __restrict__ C,
           int M, int N, int Kd) {
    __shared__ __align__(16) float As[8 * 128];   // As[k][m]
    __shared__ __align__(16) float Bs[8 * 128];   // Bs[k][n]

    const int tid  = threadIdx.x;
    const int m0   = blockIdx.y * 128;
    const int n0   = blockIdx.x * 128;
    const int arow = tid >> 1;
    const int ak4  = (tid & 1) * 4;
    const int brow = tid >> 5;
    const int bn4  = (tid & 31) * 4;
    const int tm   = tid >> 4;
    const int tn   = tid & 15;

    float acc[8][8];
    #pragma unroll
    for (int i = 0; i < 8; i++)
        #pragma unroll
        for (int j = 0; j < 8; j++) acc[i][j] = 0.f;

    for (int kt = 0; kt < Kd; kt += 8) {
        float4 av = *(const float4*)&A[(size_t)(m0 + arow) * Kd + kt + ak4];
        float4 bv = *(const float4*)&W[(size_t)(kt + brow) * N + n0 + bn4];
        __syncthreads();
        As[(ak4 + 0) * 128 + arow] = av.x;
        As[(ak4 + 1) * 128 + arow] = av.y;
        As[(ak4 + 2) * 128 + arow] = av.z;
        As[(ak4 + 3) * 128 + arow] = av.w;
        *(float4*)&Bs[brow * 128 + bn4] = bv;
        __syncthreads();

        #pragma unroll
        for (int kk = 0; kk < 8; kk++) {
            float rm[8], rn[8];
            *(float4*)&rm[0] = *(const float4*)&As[kk * 128 + tm * 8];
            *(float4*)&rm[4] = *(const float4*)&As[kk * 128 + tm * 8 + 4];
            *(float4*)&rn[0] = *(const float4*)&Bs[kk * 128 + tn * 8];
            *(float4*)&rn[4] = *(const float4*)&Bs[kk * 128 + tn * 8 + 4];
            #pragma unroll
            for (int i = 0; i < 8; i++)
                #pragma unroll
                for (int j = 0; j < 8; j++)
                    acc[i][j] = fmaf(rm[i], rn[j], acc[i][j]);
        }
    }

    float4 bv0 = *(const float4*)&bias[n0 + tn * 8];
    float4 bv1 = *(const float4*)&bias[n0 + tn * 8 + 4];
    #pragma unroll
    for (int i = 0; i < 8; i++) {
        size_t row = (size_t)(m0 + tm * 8 + i) * N + n0 + tn * 8;
        float4 o0 = {acc[i][0] + bv0.x, acc[i][1] + bv0.y,
                     acc[i][2] + bv0.z, acc[i][3] + bv0.w};
        float4 o1 = {acc[i][4] + bv1.x, acc[i][5] + bv1.y,
                     acc[i][6] + bv1.z, acc[i][7] + bv1.w};
        *(float4*)&C[row]     = o0;
        *(float4*)&C[row + 4] = o1;
    }
}

// ======================================================================
// score_gemm: raw scores S[q,k] = (Q_bh @ K_bh^T) / 8 written to atn.
// Per (b,h): M=N=2048, K=64. BM=BN=128, BK=8, 256 thr, 8x8 tile.
// Both operands loaded "transposed" (inner dim is d).
// ======================================================================
__global__ void __launch_bounds__(256)
score_gemm(const float* __restrict__ q,
           const float* __restrict__ k,
           float* __restrict__ atn) {
    __shared__ __align__(16) float As[8 * 128];   // As[d][m] (queries)
    __shared__ __align__(16) float Bs[8 * 128];   // Bs[d][n] (keys)

    const int tid = threadIdx.x;
    const int bh  = blockIdx.z;
    const int b   = bh >> 3;
    const int h   = bh & 7;
    const int m0  = blockIdx.y * 128;
    const int n0  = blockIdx.x * 128;

    const float* qb = q + (size_t)b * SS * DD + h * KK;
    const float* kb = k + (size_t)b * SS * DD + h * KK;

    const int lrow = tid >> 1;          // 0..127
    const int lc4  = (tid & 1) * 4;     // 0 or 4
    const int tm   = tid >> 4;
    const int tn   = tid & 15;

    float acc[8][8];
    #pragma unroll
    for (int i = 0; i < 8; i++)
        #pragma unroll
        for (int j = 0; j < 8; j++) acc[i][j] = 0.f;

    for (int kt = 0; kt < KK; kt += 8) {
        float4 av = *(const float4*)&qb[(size_t)(m0 + lrow) * DD + kt + lc4];
        float4 bv = *(const float4*)&kb[(size_t)(n0 + lrow) * DD + kt + lc4];
        __syncthreads();
        As[(lc4 + 0) * 128 + lrow] = av.x;
        As[(lc4 + 1) * 128 + lrow] = av.y;
        As[(lc4 + 2) * 128 + lrow] = av.z;
        As[(lc4 + 3) * 128 + lrow] = av.w;
        Bs[(lc4 + 0) * 128 + lrow] = bv.x;
        Bs[(lc4 + 1) * 128 + lrow] = bv.y;
        Bs[(lc4 + 2) * 128 + lrow] = bv.z;
        Bs[(lc4 + 3) * 128 + lrow] = bv.w;
        __syncthreads();

        #pragma unroll
        for (int kk = 0; kk < 8; kk++) {
            float rm[8], rn[8];
            *(float4*)&rm[0] = *(const float4*)&As[kk * 128 + tm * 8];
            *(float4*)&rm[4] = *(const float4*)&As[kk * 128 + tm * 8 + 4];
            *(float4*)&rn[0] = *(const float4*)&Bs[kk * 128 + tn * 8];
            *(float4*)&rn[4] = *(const float4*)&Bs[kk * 128 + tn * 8 + 4];
            #pragma unroll
            for (int i = 0; i < 8; i++)
                #pragma unroll
                for (int j = 0; j < 8; j++)
                    acc[i][j] = fmaf(rm[i], rn[j], acc[i][j]);
        }
    }

    const size_t abase = (size_t)(h * BB + b) * SS * SS;
    #pragma unroll
    for (int i = 0; i < 8; i++) {
        size_t row = abase + (size_t)(m0 + tm * 8 + i) * SS + n0 + tn * 8;
        float4 o0 = {acc[i][0] * 0.125f, acc[i][1] * 0.125f,
                     acc[i][2] * 0.125f, acc[i][3] * 0.125f};
        float4 o1 = {acc[i][4] * 0.125f, acc[i][5] * 0.125f,
                     acc[i][6] * 0.125f, acc[i][7] * 0.125f};
        *(float4*)&atn[row]     = o0;
        *(float4*)&atn[row + 4] = o1;
    }
}

// ======================================================================
// softmax_rows: in-place row softmax on p (row length 2048).
// One block (256 thr) per row, 8 elems/thread, fast_exp (no MUFU).
// ======================================================================
__device__ __forceinline__ float blockReduceSum256(float v, float* red) {
    #pragma unroll
    for (int o = 16; o; o >>= 1) v += __shfl_xor_sync(0xffffffff, v, o);
    int w = threadIdx.x >> 5;
    if ((threadIdx.x & 31) == 0) red[w] = v;
    __syncthreads();
    float r = 0.f;
    if (threadIdx.x < 32) {
        r = (threadIdx.x < 8) ? red[threadIdx.x] : 0.f;
        #pragma unroll
        for (int o = 4; o; o >>= 1) r += __shfl_xor_sync(0xffffffff, r, o);
        if (threadIdx.x == 0) red[0] = r;
    }
    __syncthreads();
    float out = red[0];
    __syncthreads();
    return out;
}

__device__ __forceinline__ float blockReduceMax256(float v, float* red) {
    #pragma unroll
    for (int o = 16; o; o >>= 1) v = fmaxf(v, __shfl_xor_sync(0xffffffff, v, o));
    int w = threadIdx.x >> 5;
    if ((threadIdx.x & 31) == 0) red[w] = v;
    __syncthreads();
    float r = -1e30f;
    if (threadIdx.x < 32) {
        r = (threadIdx.x < 8) ? red[threadIdx.x] : -1e30f;
        #pragma unroll
        for (int o = 4; o; o >>= 1) r = fmaxf(r, __shfl_xor_sync(0xffffffff, r, o));
        if (threadIdx.x == 0) red[0] = r;
    }
    __syncthreads();
    float out = red[0];
    __syncthreads();
    return out;
}

__global__ void __launch_bounds__(256)
softmax_rows(float* __restrict__ p) {
    __shared__ float red[32];
    size_t base = (size_t)blockIdx.x * SS + threadIdx.x * 8;

    float4 a = *(const float4*)&p[base];
    float4 c = *(const float4*)&p[base + 4];

    float mx = fmaxf(fmaxf(fmaxf(a.x, a.y), fmaxf(a.z, a.w)),
                     fmaxf(fmaxf(c.x, c.y), fmaxf(c.z, c.w)));
    mx = blockReduceMax256(mx, red);

    a.x = fast_exp(a.x - mx); a.y = fast_exp(a.y - mx);
    a.z = fast_exp(a.z - mx); a.w = fast_exp(a.w - mx);
    c.x = fast_exp(c.x - mx); c.y = fast_exp(c.y - mx);
    c.z = fast_exp(c.z - mx); c.w = fast_exp(c.w - mx);

    float sum = (a.x + a.y) + (a.z + a.w) + (c.x + c.y) + (c.z + c.w);
    sum = blockReduceSum256(sum, red);
    float inv = 1.f / sum;

    a.x *= inv; a.y *= inv; a.z *= inv; a.w *= inv;
    c.x *= inv; c.y *= inv; c.z *= inv; c.w *= inv;
    *(float4*)&p[base]     = a;
    *(float4*)&p[base + 4] = c;
}

// ======================================================================
// ctx_gemm: per (b,h): ctx[2048,64] = P[2048,2048] @ V[2048,64]
// BM=128, BN=64, BK=32, 256 threads, 8x4 reg tile.
// ======================================================================
__global__ void __launch_bounds__(256)
ctx_gemm(const float* __restrict__ P,
         const float* __restrict__ v,
         float* __restrict__ ctx) {
    __shared__ __align__(16) float Ps[32 * 132];  // Ps[s][q]
    __shared__ __align__(16) float Vs[32 * 64];   // Vs[s][d]

    const int tid = threadIdx.x;
    const int bh  = blockIdx.x;
    const int b   = bh >> 3;
    const int h   = bh & 7;
    const int q0  = blockIdx.y * 128;
    const size_t pbase = (size_t)(h * BB + b) * SS * SS;

    const int tq = tid >> 4;
    const int td = tid & 15;

    float acc[8][4];
    #pragma unroll
    for (int i = 0; i < 8; i++)
        #pragma unroll
        for (int j = 0; j < 4; j++) acc[i][j] = 0.f;

    for (int c = 0; c < SS; c += 32) {
        __syncthreads();
        #pragma unroll
        for (int i = 0; i < 4; i++) {
            int lin = tid + i * 256;
            int qr = lin >> 3, s4 = (lin & 7) * 4;
            float4 pv = *(const float4*)&P[pbase + (size_t)(q0 + qr) * SS + c + s4];
            Ps[(s4 + 0) * 132 + qr] = pv.x;
            Ps[(s4 + 1) * 132 + qr] = pv.y;
            Ps[(s4 + 2) * 132 + qr] = pv.z;
            Ps[(s4 + 3) * 132 + qr] = pv.w;
        }
        #pragma unroll
        for (int i = 0; i < 2; i++) {
            int lin = tid + i * 256;
            int s = lin >> 4, d4 = (lin & 15) * 4;
            *(float4*)&Vs[s * 64 + d4] =
                *(const float4*)&v[(size_t)(b * SS + c + s) * DD + h * KK + d4];
        }
        __syncthreads();

        #pragma unroll 8
        for (int s = 0; s < 32; s++) {
            float4 m0 = *(const float4*)&Ps[s * 132 + tq * 8];
            float4 m1 = *(const float4*)&Ps[s * 132 + tq * 8 + 4];
            float4 n0 = *(const float4*)&Vs[s * 64 + td * 4];
            float ma[8] = {m0.x, m0.y, m0.z, m0.w, m1.x, m1.y, m1.z, m1.w};
            float na[4] = {n0.x, n0.y, n0.z, n0.w};
            #pragma unroll
            for (int i = 0; i < 8; i++)
                #pragma unroll
                for (int j = 0; j < 4; j++)
                    acc[i][j] = fmaf(ma[i], na[j], acc[i][j]);
        }
    }

    #pragma unroll
    for (int i = 0; i < 8; i++) {
        float4 o = {acc[i][0], acc[i][1], acc[i][2], acc[i][3]};
        *(float4*)&ctx[(size_t)(b * SS + q0 + tq * 8 + i) * DD + h * KK + td * 4] = o;
    }
}

// ======================================================================
// FFN1 GEMM + ReLU: C[M,64] = relu(A[M,512] @ W[512,64] + bias)
// ======================================================================
__global__ void __launch_bounds__(256)
ffn1_gemm(const float* __restrict__ A,
          const float* __restrict__ W,
          const float* __restrict__ bias,
          float* __restrict__ C) {
    __shared__ __align__(16) float As[32 * 132];
    __shared__ __align__(16) float Ws[32 * 64];

    const int tid = threadIdx.x;
    const int m0  = blockIdx.x * 128;
    const int tq = tid >> 4;
    const int td = tid & 15;

    float acc[8][4];
    #pragma unroll
    for (int i = 0; i < 8; i++)
        #pragma unroll
        for (int j = 0; j < 4; j++) acc[i][j] = 0.f;

    for (int c = 0; c < DD; c += 32) {
        __syncthreads();
        #pragma unroll
        for (int i = 0; i < 4; i++) {
            int lin = tid + i * 256;
            int qr = lin >> 3, k4 = (lin & 7) * 4;
            float4 av = *(const float4*)&A[(size_t)(m0 + qr) * DD + c + k4];
            As[(k4 + 0) * 132 + qr] = av.x;
            As[(k4 + 1) * 132 + qr] = av.y;
            As[(k4 + 2) * 132 + qr] = av.z;
            As[(k4 + 3) * 132 + qr] = av.w;
        }
        #pragma unroll
        for (int i = 0; i < 2; i++) {
            int lin = tid + i * 256;
            int kr = lin >> 4, n4 = (lin & 15) * 4;
            *(float4*)&Ws[kr * 64 + n4] = *(const float4*)&W[(size_t)(c + kr) * FF + n4];
        }
        __syncthreads();

        #pragma unroll 8
        for (int s = 0; s < 32; s++) {
            float4 m0v = *(const float4*)&As[s * 132 + tq * 8];
            float4 m1v = *(const float4*)&As[s * 132 + tq * 8 + 4];
            float4 n0v = *(const float4*)&Ws[s * 64 + td * 4];
            float ma[8] = {m0v.x, m0v.y, m0v.z, m0v.w, m1v.x, m1v.y, m1v.z, m1v.w};
            float na[4] = {n0v.x, n0v.y, n0v.z, n0v.w};
            #pragma unroll
            for (int i = 0; i < 8; i++)
                #pragma unroll
                for (int j = 0; j < 4; j++)
                    acc[i][j] = fmaf(ma[i], na[j], acc[i][j]);
        }
    }

    float4 bv = *(const float4*)&bias[td * 4];
    float ba[4] = {bv.x, bv.y, bv.z, bv.w};
    #pragma unroll
    for (int i = 0; i < 8; i++) {
        float4 o = {fmaxf(acc[i][0] + ba[0], 0.f), fmaxf(acc[i][1] + ba[1], 0.f),
                    fmaxf(acc[i][2] + ba[2], 0.f), fmaxf(acc[i][3] + ba[3], 0.f)};
        *(float4*)&C[(size_t)(m0 + tq * 8 + i) * FF + td * 4] = o;
    }
}

// ======================================================================
// mha_out = LN(tmp + x) (g_mha,b_mha); h = LN(mha_out + x) (g_net1,b_net1)
// ======================================================================
__global__ void addln2_kernel(const float* __restrict__ tmp,
                              const float* __restrict__ x,
                              const float* __restrict__ gm, const float* __restrict__ bm,
                              const float* __restrict__ g1, const float* __restrict__ b1,
                              float* __restrict__ hout) {
    __shared__ float red[32];
    const int r = blockIdx.x;
    const int d0 = threadIdx.x, d1 = threadIdx.x + 256;
    size_t base = (size_t)r * DD;

    float x0 = x[base + d0], x1 = x[base + d1];
    float p0 = tmp[base + d0] + x0;
    float p1 = tmp[base + d1] + x1;

    float mean = blockReduceSum256(p0 + p1, red) * (1.f / DD);
    float dv0 = p0 - mean, dv1 = p1 - mean;
    float var = blockReduceSum256(dv0 * dv0 + dv1 * dv1, red) * (1.f / DD);
    float rstd = rsqrtf(var + EPS);

    float m0 = dv0 * rstd * gm[d0] + bm[d0];
    float m1 = dv1 * rstd * gm[d1] + bm[d1];

    float t0 = m0 + x0, t1 = m1 + x1;
    float mean2 = blockReduceSum256(t0 + t1, red) * (1.f / DD);
    float e0 = t0 - mean2, e1 = t1 - mean2;
    float var2 = blockReduceSum256(e0 * e0 + e1 * e1, red) * (1.f / DD);
    float rstd2 = rsqrtf(var2 + EPS);

    hout[base + d0] = e0 * rstd2 * g1[d0] + b1[d0];
    hout[base + d1] = e1 * rstd2 * g1[d1] + b1[d1];
}

// ======================================================================
// out = LN(tmp + h) with (g,b). One block per row.
// ======================================================================
__global__ void addln1_kernel(const float* __restrict__ tmp,
                              const float* __restrict__ h,
                              const float* __restrict__ g, const float* __restrict__ b,
                              float* __restrict__ out) {
    __shared__ float red[32];
    const int r = blockIdx.x;
    const int d0 = threadIdx.x, d1 = threadIdx.x + 256;
    size_t base = (size_t)r * DD;

    float v0 = tmp[base + d0] + h[base + d0];
    float v1 = tmp[base + d1] + h[base + d1];

    float mean = blockReduceSum256(v0 + v1, red) * (1.f / DD);
    float e0 = v0 - mean, e1 = v1 - mean;
    float var = blockReduceSum256(e0 * e0 + e1 * e1, red) * (1.f / DD);
    float rstd = rsqrtf(var + EPS);

    out[base + d0] = e0 * rstd * g[d0] + b[d0];
    out[base + d1] = e1 * rstd * g[d1] + b[d1];
}

// ======================================================================
// launch
// ======================================================================
extern "C" void kernel_launch(void* const* d_in, const int* in_sizes, int n_in,
                              void* d_out, int out_size) {
    const float* x      = (const float*)d_in[0];
    const float* Wq     = (const float*)d_in[1];
    const float* bq     = (const float*)d_in[2];
    const float* Wk     = (const float*)d_in[3];
    const float* bk     = (const float*)d_in[4];
    const float* Wv     = (const float*)d_in[5];
    const float* bv     = (const float*)d_in[6];
    const float* Wo     = (const float*)d_in[7];
    const float* bo     = (const float*)d_in[8];
    const float* g_mha  = (const float*)d_in[9];
    const float* b_mha  = (const float*)d_in[10];
    const float* g_net1 = (const float*)d_in[11];
    const float* b_net1 = (const float*)d_in[12];
    const float* W1     = (const float*)d_in[13];
    const float* b1     = (const float*)d_in[14];
    const float* W2     = (const float*)d_in[15];
    const float* b2     = (const float*)d_in[16];
    const float* g_net2 = (const float*)d_in[17];
    const float* b_net2 = (const float*)d_in[18];

    float* qb;  cudaGetSymbolAddress((void**)&qb,  g_q);
    float* kb;  cudaGetSymbolAddress((void**)&kb,  g_k);
    float* vb;  cudaGetSymbolAddress((void**)&vb,  g_v);
    float* ctx; cudaGetSymbolAddress((void**)&ctx, g_ctx);
    float* tmp; cudaGetSymbolAddress((void**)&tmp, g_tmp);
    float* hb;  cudaGetSymbolAddress((void**)&hb,  g_h);
    float* hhb; cudaGetSymbolAddress((void**)&hhb, g_hh);

    const size_t OUT_ELEMS = (size_t)BB * SS * DD;
    float* outp = (float*)d_out;
    float* atnp = (float*)d_out + OUT_ELEMS;   // probs live in the output buffer

    dim3 gproj(DD / 128, MT / 128);            // 4 x 64
    sgemm_bias<<<gproj, 256>>>(x, Wq, bq, qb, MT, DD, DD);
    sgemm_bias<<<gproj, 256>>>(x, Wk, bk, kb, MT, DD, DD);
    sgemm_bias<<<gproj, 256>>>(x, Wv, bv, vb, MT, DD, DD);

    dim3 gscore(SS / 128, SS / 128, BB * HH);  // 16 x 16 x 32
    score_gemm<<<gscore, 256>>>(qb, kb, atnp);

    softmax_rows<<<BB * HH * SS, 256>>>(atnp);

    dim3 gctx(BB * HH, SS / 128);              // 32 x 16
    ctx_gemm<<<gctx, 256>>>(atnp, vb, ctx);

    sgemm_bias<<<gproj, 256>>>(ctx, Wo, bo, tmp, MT, DD, DD);

    addln2_kernel<<<MT, 256>>>(tmp, x, g_mha, b_mha, g_net1, b_net1, hb);

    ffn1_gemm<<<MT / 128, 256>>>(hb, W1, b1, hhb);

    sgemm_bias<<<gproj, 256>>>(hhb, W2, b2, tmp, MT, DD, FF);

    addln1_kernel<<<MT, 256>>>(tmp, hb, g_net2, b_net2, outp);
}

// round 9
// speedup vs baseline: 2.4633x; 1.1867x over previous
#include <cuda_runtime.h>
#include <cuda_bf16.h>
#include <math.h>
#include <cstdint>

// Problem constants
#define BB 4
#define SS 2048
#define DD 512
#define HH 8
#define KK 64
#define FF 64
#define MT (BB*SS)
#define EPS 1e-5f

// -------- scratch (no allocation allowed) --------
__device__ float g_q  [MT*DD];
__device__ float g_k  [MT*DD];
__device__ float g_v  [MT*DD];
__device__ float g_ctx[MT*DD];
__device__ float g_tmp[MT*DD];
__device__ float g_h  [MT*DD];
__device__ float g_hh [MT*FF];
__device__ __nv_bfloat16 g_qhi[MT*DD];
__device__ __nv_bfloat16 g_qlo[MT*DD];
__device__ __nv_bfloat16 g_khi[MT*DD];
__device__ __nv_bfloat16 g_klo[MT*DD];

// ======================================================================
// warp-level MMA helpers (sm_80+ PTX, runs on tensor pipe)
// ======================================================================
__device__ __forceinline__ uint32_t smem_u32(const void* p) {
    uint32_t a;
    asm("{ .reg .u64 t; cvta.to.shared.u64 t, %1; cvt.u32.u64 %0, t; }"
        : "=r"(a) : "l"(p));
    return a;
}

__device__ __forceinline__ void ldsm_x4(uint32_t r[4], uint32_t addr) {
    asm volatile("ldmatrix.sync.aligned.m8n8.x4.shared.b16 {%0,%1,%2,%3}, [%4];"
        : "=r"(r[0]), "=r"(r[1]), "=r"(r[2]), "=r"(r[3]) : "r"(addr));
}
__device__ __forceinline__ void ldsm_x2(uint32_t r[2], uint32_t addr) {
    asm volatile("ldmatrix.sync.aligned.m8n8.x2.shared.b16 {%0,%1}, [%2];"
        : "=r"(r[0]), "=r"(r[1]) : "r"(addr));
}
__device__ __forceinline__ void mma_bf16(float d[4], const uint32_t a[4],
                                         const uint32_t b[2]) {
    asm volatile("mma.sync.aligned.m16n8k16.row.col.f32.bf16.bf16.f32 "
        "{%0,%1,%2,%3}, {%4,%5,%6,%7}, {%8,%9}, {%0,%1,%2,%3};"
        : "+f"(d[0]), "+f"(d[1]), "+f"(d[2]), "+f"(d[3])
        : "r"(a[0]), "r"(a[1]), "r"(a[2]), "r"(a[3]), "r"(b[0]), "r"(b[1]));
}

// ======================================================================
// split into bf16 hi/lo (with scale folded in)
// ======================================================================
__global__ void __launch_bounds__(256)
split_bf16(const float* __restrict__ src,
           __nv_bfloat16* __restrict__ hi,
           __nv_bfloat16* __restrict__ lo,
           float scale) {
    int i = (blockIdx.x * 256 + threadIdx.x) * 4;
    float4 v = *(const float4*)&src[i];
    v.x *= scale; v.y *= scale; v.z *= scale; v.w *= scale;
    __nv_bfloat16 hx = __float2bfloat16(v.x), hy = __float2bfloat16(v.y);
    __nv_bfloat16 hz = __float2bfloat16(v.z), hw = __float2bfloat16(v.w);
    __nv_bfloat162 h0 = {hx, hy}, h1 = {hz, hw};
    __nv_bfloat162 l0 = {__float2bfloat16(v.x - __bfloat162float(hx)),
                         __float2bfloat16(v.y - __bfloat162float(hy))};
    __nv_bfloat162 l1 = {__float2bfloat16(v.z - __bfloat162float(hz)),
                         __float2bfloat16(v.w - __bfloat162float(hw))};
    *(__nv_bfloat162*)&hi[i]     = h0;
    *(__nv_bfloat162*)&hi[i + 2] = h1;
    *(__nv_bfloat162*)&lo[i]     = l0;
    *(__nv_bfloat162*)&lo[i + 2] = l1;
}

// ======================================================================
// score_hmma: tensor-core scores via mma.sync (bf16 3-term compensated).
// CTA = 128 q x 128 k tile of one (b,h). 8 warps, each 64x32.
// smem: Qhi|Qlo|Khi|Klo, each [128 rows][72 halves] (144B stride,
// conflict-free for ldmatrix). Q pre-scaled by 1/8.
// ======================================================================
#define RST 72              // smem row stride in halves
#define RSB 144             // row stride bytes
#define TILE_HALVES (128 * RST)
#define SH_SMEM (4 * TILE_HALVES * 2)   // 73728 B

__global__ void __launch_bounds__(256)
score_hmma(const __nv_bfloat16* __restrict__ qhi,
           const __nv_bfloat16* __restrict__ qlo,
           const __nv_bfloat16* __restrict__ khi,
           const __nv_bfloat16* __restrict__ klo,
           float* __restrict__ atn) {
    extern __shared__ __nv_bfloat16 sh[];
    __nv_bfloat16* sQhi = sh;
    __nv_bfloat16* sQlo = sh + TILE_HALVES;
    __nv_bfloat16* sKhi = sh + 2 * TILE_HALVES;
    __nv_bfloat16* sKlo = sh + 3 * TILE_HALVES;

    const int tid  = threadIdx.x;
    const int wid  = tid >> 5, lane = tid & 31;
    const int bh   = blockIdx.z, b = bh >> 3, h = bh & 7;
    const int m0   = blockIdx.y * 128;
    const int n0   = blockIdx.x * 128;

    // ---- load tiles: 128 rows x 64 halves, 8-half (16B) chunks ----
    #pragma unroll
    for (int i = 0; i < 4; i++) {
        int idx = tid + i * 256;          // 0..1023
        int row = idx >> 3, c8 = idx & 7; // col group (8 halves)
        int soff = row * RST + c8 * 8;
        size_t qg = (size_t)(b * SS + m0 + row) * DD + h * KK + c8 * 8;
        size_t kg = (size_t)(b * SS + n0 + row) * DD + h * KK + c8 * 8;
        *(uint4*)&sQhi[soff] = *(const uint4*)&qhi[qg];
        *(uint4*)&sQlo[soff] = *(const uint4*)&qlo[qg];
        *(uint4*)&sKhi[soff] = *(const uint4*)&khi[kg];
        *(uint4*)&sKlo[soff] = *(const uint4*)&klo[kg];
    }
    __syncthreads();

    // warp tile: rows wr*64, cols wc*32
    const int wr = wid >> 2, wc = wid & 3;
    const int wm = wr * 64, wn = wc * 32;

    float acc[4][4][4];
    #pragma unroll
    for (int mt = 0; mt < 4; mt++)
        #pragma unroll
        for (int nt = 0; nt < 4; nt++)
            #pragma unroll
            for (int e = 0; e < 4; e++) acc[mt][nt][e] = 0.f;

    const uint32_t qhiA = smem_u32(sQhi), qloA = smem_u32(sQlo);
    const uint32_t khiA = smem_u32(sKhi), kloA = smem_u32(sKlo);
    // ldmatrix lane addressing
    const int la16 = lane & 15;
    const uint32_t a_off = (uint32_t)((wm + la16) * RSB + (lane >> 4) * 16);
    const uint32_t b_off = (uint32_t)((wn + (la16 & 7)) * RSB + ((la16 >> 3) & 1) * 16);

    const uint32_t qbases[3] = {qhiA, qhiA, qloA};
    const uint32_t kbases[3] = {khiA, kloA, khiA};

    #pragma unroll
    for (int t = 0; t < 3; t++) {
        const uint32_t qb = qbases[t], kb = kbases[t];
        #pragma unroll
        for (int kkt = 0; kkt < 4; kkt++) {
            const uint32_t kbyte = kkt * 32;   // 16 halves
            uint32_t afrag[4][4], bfrag[4][2];
            #pragma unroll
            for (int mt = 0; mt < 4; mt++)
                ldsm_x4(afrag[mt], qb + a_off + mt * 16 * RSB + kbyte);
            #pragma unroll
            for (int nt = 0; nt < 4; nt++)
                ldsm_x2(bfrag[nt], kb + b_off + nt * 8 * RSB + kbyte);
            #pragma unroll
            for (int mt = 0; mt < 4; mt++)
                #pragma unroll
                for (int nt = 0; nt < 4; nt++)
                    mma_bf16(acc[mt][nt], afrag[mt], bfrag[nt]);
        }
    }

    // ---- epilogue: c-fragment direct stores (float2, 8B sectors full) ----
    const size_t abase = (size_t)(h * BB + b) * SS * SS;
    const int rq = lane >> 2;          // 0..7
    const int cq = (lane & 3) * 2;     // 0,2,4,6
    #pragma unroll
    for (int mt = 0; mt < 4; mt++) {
        #pragma unroll
        for (int nt = 0; nt < 4; nt++) {
            size_t r0 = abase + (size_t)(m0 + wm + mt * 16 + rq) * SS + n0 + wn + nt * 8 + cq;
            *(float2*)&atn[r0]          = make_float2(acc[mt][nt][0], acc[mt][nt][1]);
            *(float2*)&atn[r0 + 8 * SS] = make_float2(acc[mt][nt][2], acc[mt][nt][3]);
        }
    }
}

// ======================================================================
// Classic SGEMM: C[M,N] = A[M,Kd] @ W[Kd,N] + bias
// ======================================================================
__global__ void __launch_bounds__(256)
sgemm_bias(const float* __restrict__ A,
           const float* __restrict__ W,
           const float* __restrict__ bias,
           float* __restrict__ C,
           int M, int N, int Kd) {
    __shared__ __align__(16) float As[8 * 128];
    __shared__ __align__(16) float Bs[8 * 128];

    const int tid  = threadIdx.x;
    const int m0   = blockIdx.y * 128;
    const int n0   = blockIdx.x * 128;
    const int arow = tid >> 1;
    const int ak4  = (tid & 1) * 4;
    const int brow = tid >> 5;
    const int bn4  = (tid & 31) * 4;
    const int tm   = tid >> 4;
    const int tn   = tid & 15;

    float acc[8][8];
    #pragma unroll
    for (int i = 0; i < 8; i++)
        #pragma unroll
        for (int j = 0; j < 8; j++) acc[i][j] = 0.f;

    for (int kt = 0; kt < Kd; kt += 8) {
        float4 av = *(const float4*)&A[(size_t)(m0 + arow) * Kd + kt + ak4];
        float4 bv = *(const float4*)&W[(size_t)(kt + brow) * N + n0 + bn4];
        __syncthreads();
        As[(ak4 + 0) * 128 + arow] = av.x;
        As[(ak4 + 1) * 128 + arow] = av.y;
        As[(ak4 + 2) * 128 + arow] = av.z;
        As[(ak4 + 3) * 128 + arow] = av.w;
        *(float4*)&Bs[brow * 128 + bn4] = bv;
        __syncthreads();

        #pragma unroll
        for (int kk = 0; kk < 8; kk++) {
            float rm[8], rn[8];
            *(float4*)&rm[0] = *(const float4*)&As[kk * 128 + tm * 8];
            *(float4*)&rm[4] = *(const float4*)&As[kk * 128 + tm * 8 + 4];
            *(float4*)&rn[0] = *(const float4*)&Bs[kk * 128 + tn * 8];
            *(float4*)&rn[4] = *(const float4*)&Bs[kk * 128 + tn * 8 + 4];
            #pragma unroll
            for (int i = 0; i < 8; i++)
                #pragma unroll
                for (int j = 0; j < 8; j++)
                    acc[i][j] = fmaf(rm[i], rn[j], acc[i][j]);
        }
    }

    float4 bv0 = *(const float4*)&bias[n0 + tn * 8];
    float4 bv1 = *(const float4*)&bias[n0 + tn * 8 + 4];
    #pragma unroll
    for (int i = 0; i < 8; i++) {
        size_t row = (size_t)(m0 + tm * 8 + i) * N + n0 + tn * 8;
        float4 o0 = {acc[i][0] + bv0.x, acc[i][1] + bv0.y,
                     acc[i][2] + bv0.z, acc[i][3] + bv0.w};
        float4 o1 = {acc[i][4] + bv1.x, acc[i][5] + bv1.y,
                     acc[i][6] + bv1.z, acc[i][7] + bv1.w};
        *(float4*)&C[row]     = o0;
        *(float4*)&C[row + 4] = o1;
    }
}

// ======================================================================
// fast exp on FMA/ALU pipes (no MUFU)
// ======================================================================
__device__ __forceinline__ float fast_exp(float x) {
    x = fmaxf(x, -87.0f);
    float y0 = x * 1.4426950408889634f;
    float z  = y0 + 12582912.0f;
    float t  = z - 12582912.0f;
    float f  = y0 - t;
    int   n  = __float_as_int(z) - 0x4B400000;
    float p  = 0.0013333558f;
    p = fmaf(p, f, 0.0096181291f);
    p = fmaf(p, f, 0.0555041087f);
    p = fmaf(p, f, 0.2402265069f);
    p = fmaf(p, f, 0.6931471806f);
    p = fmaf(p, f, 1.0f);
    return p * __int_as_float((n + 127) << 23);
}

__device__ __forceinline__ float blockReduceSum256(float v, float* red) {
    #pragma unroll
    for (int o = 16; o; o >>= 1) v += __shfl_xor_sync(0xffffffff, v, o);
    int w = threadIdx.x >> 5;
    if ((threadIdx.x & 31) == 0) red[w] = v;
    __syncthreads();
    float r = 0.f;
    if (threadIdx.x < 32) {
        r = (threadIdx.x < 8) ? red[threadIdx.x] : 0.f;
        #pragma unroll
        for (int o = 4; o; o >>= 1) r += __shfl_xor_sync(0xffffffff, r, o);
        if (threadIdx.x == 0) red[0] = r;
    }
    __syncthreads();
    float out = red[0];
    __syncthreads();
    return out;
}

__device__ __forceinline__ float blockReduceMax256(float v, float* red) {
    #pragma unroll
    for (int o = 16; o; o >>= 1) v = fmaxf(v, __shfl_xor_sync(0xffffffff, v, o));
    int w = threadIdx.x >> 5;
    if ((threadIdx.x & 31) == 0) red[w] = v;
    __syncthreads();
    float r = -1e30f;
    if (threadIdx.x < 32) {
        r = (threadIdx.x < 8) ? red[threadIdx.x] : -1e30f;
        #pragma unroll
        for (int o = 4; o; o >>= 1) r = fmaxf(r, __shfl_xor_sync(0xffffffff, r, o));
        if (threadIdx.x == 0) red[0] = r;
    }
    __syncthreads();
    float out = red[0];
    __syncthreads();
    return out;
}

__global__ void __launch_bounds__(256)
softmax_rows(float* __restrict__ p) {
    __shared__ float red[32];
    size_t base = (size_t)blockIdx.x * SS + threadIdx.x * 8;

    float4 a = *(const float4*)&p[base];
    float4 c = *(const float4*)&p[base + 4];

    float mx = fmaxf(fmaxf(fmaxf(a.x, a.y), fmaxf(a.z, a.w)),
                     fmaxf(fmaxf(c.x, c.y), fmaxf(c.z, c.w)));
    mx = blockReduceMax256(mx, red);

    a.x = fast_exp(a.x - mx); a.y = fast_exp(a.y - mx);
    a.z = fast_exp(a.z - mx); a.w = fast_exp(a.w - mx);
    c.x = fast_exp(c.x - mx); c.y = fast_exp(c.y - mx);
    c.z = fast_exp(c.z - mx); c.w = fast_exp(c.w - mx);

    float sum = (a.x + a.y) + (a.z + a.w) + (c.x + c.y) + (c.z + c.w);
    sum = blockReduceSum256(sum, red);
    float inv = 1.f / sum;

    a.x *= inv; a.y *= inv; a.z *= inv; a.w *= inv;
    c.x *= inv; c.y *= inv; c.z *= inv; c.w *= inv;
    *(float4*)&p[base]     = a;
    *(float4*)&p[base + 4] = c;
}

// ======================================================================
// ctx_gemm: per (b,h): ctx = P @ V
// ======================================================================
__global__ void __launch_bounds__(256)
ctx_gemm(const float* __restrict__ P,
         const float* __restrict__ v,
         float* __restrict__ ctx) {
    __shared__ __align__(16) float Ps[32 * 132];
    __shared__ __align__(16) float Vs[32 * 64];

    const int tid = threadIdx.x;
    const int bh  = blockIdx.x;
    const int b   = bh >> 3;
    const int h   = bh & 7;
    const int q0  = blockIdx.y * 128;
    const size_t pbase = (size_t)(h * BB + b) * SS * SS;

    const int tq = tid >> 4;
    const int td = tid & 15;

    float acc[8][4];
    #pragma unroll
    for (int i = 0; i < 8; i++)
        #pragma unroll
        for (int j = 0; j < 4; j++) acc[i][j] = 0.f;

    for (int c = 0; c < SS; c += 32) {
        __syncthreads();
        #pragma unroll
        for (int i = 0; i < 4; i++) {
            int lin = tid + i * 256;
            int qr = lin >> 3, s4 = (lin & 7) * 4;
            float4 pv = *(const float4*)&P[pbase + (size_t)(q0 + qr) * SS + c + s4];
            Ps[(s4 + 0) * 132 + qr] = pv.x;
            Ps[(s4 + 1) * 132 + qr] = pv.y;
            Ps[(s4 + 2) * 132 + qr] = pv.z;
            Ps[(s4 + 3) * 132 + qr] = pv.w;
        }
        #pragma unroll
        for (int i = 0; i < 2; i++) {
            int lin = tid + i * 256;
            int s = lin >> 4, d4 = (lin & 15) * 4;
            *(float4*)&Vs[s * 64 + d4] =
                *(const float4*)&v[(size_t)(b * SS + c + s) * DD + h * KK + d4];
        }
        __syncthreads();

        #pragma unroll 8
        for (int s = 0; s < 32; s++) {
            float4 m0 = *(const float4*)&Ps[s * 132 + tq * 8];
            float4 m1 = *(const float4*)&Ps[s * 132 + tq * 8 + 4];
            float4 n0 = *(const float4*)&Vs[s * 64 + td * 4];
            float ma[8] = {m0.x, m0.y, m0.z, m0.w, m1.x, m1.y, m1.z, m1.w};
            float na[4] = {n0.x, n0.y, n0.z, n0.w};
            #pragma unroll
            for (int i = 0; i < 8; i++)
                #pragma unroll
                for (int j = 0; j < 4; j++)
                    acc[i][j] = fmaf(ma[i], na[j], acc[i][j]);
        }
    }

    #pragma unroll
    for (int i = 0; i < 8; i++) {
        float4 o = {acc[i][0], acc[i][1], acc[i][2], acc[i][3]};
        *(float4*)&ctx[(size_t)(b * SS + q0 + tq * 8 + i) * DD + h * KK + td * 4] = o;
    }
}

// ======================================================================
// FFN1 GEMM + ReLU
// ======================================================================
__global__ void __launch_bounds__(256)
ffn1_gemm(const float* __restrict__ A,
          const float* __restrict__ W,
          const float* __restrict__ bias,
          float* __restrict__ C) {
    __shared__ __align__(16) float As[32 * 132];
    __shared__ __align__(16) float Ws[32 * 64];

    const int tid = threadIdx.x;
    const int m0  = blockIdx.x * 128;
    const int tq = tid >> 4;
    const int td = tid & 15;

    float acc[8][4];
    #pragma unroll
    for (int i = 0; i < 8; i++)
        #pragma unroll
        for (int j = 0; j < 4; j++) acc[i][j] = 0.f;

    for (int c = 0; c < DD; c += 32) {
        __syncthreads();
        #pragma unroll
        for (int i = 0; i < 4; i++) {
            int lin = tid + i * 256;
            int qr = lin >> 3, k4 = (lin & 7) * 4;
            float4 av = *(const float4*)&A[(size_t)(m0 + qr) * DD + c + k4];
            As[(k4 + 0) * 132 + qr] = av.x;
            As[(k4 + 1) * 132 + qr] = av.y;
            As[(k4 + 2) * 132 + qr] = av.z;
            As[(k4 + 3) * 132 + qr] = av.w;
        }
        #pragma unroll
        for (int i = 0; i < 2; i++) {
            int lin = tid + i * 256;
            int kr = lin >> 4, n4 = (lin & 15) * 4;
            *(float4*)&Ws[kr * 64 + n4] = *(const float4*)&W[(size_t)(c + kr) * FF + n4];
        }
        __syncthreads();

        #pragma unroll 8
        for (int s = 0; s < 32; s++) {
            float4 m0v = *(const float4*)&As[s * 132 + tq * 8];
            float4 m1v = *(const float4*)&As[s * 132 + tq * 8 + 4];
            float4 n0v = *(const float4*)&Ws[s * 64 + td * 4];
            float ma[8] = {m0v.x, m0v.y, m0v.z, m0v.w, m1v.x, m1v.y, m1v.z, m1v.w};
            float na[4] = {n0v.x, n0v.y, n0v.z, n0v.w};
            #pragma unroll
            for (int i = 0; i < 8; i++)
                #pragma unroll
                for (int j = 0; j < 4; j++)
                    acc[i][j] = fmaf(ma[i], na[j], acc[i][j]);
        }
    }

    float4 bv = *(const float4*)&bias[td * 4];
    float ba[4] = {bv.x, bv.y, bv.z, bv.w};
    #pragma unroll
    for (int i = 0; i < 8; i++) {
        float4 o = {fmaxf(acc[i][0] + ba[0], 0.f), fmaxf(acc[i][1] + ba[1], 0.f),
                    fmaxf(acc[i][2] + ba[2], 0.f), fmaxf(acc[i][3] + ba[3], 0.f)};
        *(float4*)&C[(size_t)(m0 + tq * 8 + i) * FF + td * 4] = o;
    }
}

// ======================================================================
// LN kernels
// ======================================================================
__global__ void addln2_kernel(const float* __restrict__ tmp,
                              const float* __restrict__ x,
                              const float* __restrict__ gm, const float* __restrict__ bm,
                              const float* __restrict__ g1, const float* __restrict__ b1,
                              float* __restrict__ hout) {
    __shared__ float red[32];
    const int r = blockIdx.x;
    const int d0 = threadIdx.x, d1 = threadIdx.x + 256;
    size_t base = (size_t)r * DD;

    float x0 = x[base + d0], x1 = x[base + d1];
    float p0 = tmp[base + d0] + x0;
    float p1 = tmp[base + d1] + x1;

    float mean = blockReduceSum256(p0 + p1, red) * (1.f / DD);
    float dv0 = p0 - mean, dv1 = p1 - mean;
    float var = blockReduceSum256(dv0 * dv0 + dv1 * dv1, red) * (1.f / DD);
    float rstd = rsqrtf(var + EPS);

    float m0 = dv0 * rstd * gm[d0] + bm[d0];
    float m1 = dv1 * rstd * gm[d1] + bm[d1];

    float t0 = m0 + x0, t1 = m1 + x1;
    float mean2 = blockReduceSum256(t0 + t1, red) * (1.f / DD);
    float e0 = t0 - mean2, e1 = t1 - mean2;
    float var2 = blockReduceSum256(e0 * e0 + e1 * e1, red) * (1.f / DD);
    float rstd2 = rsqrtf(var2 + EPS);

    hout[base + d0] = e0 * rstd2 * g1[d0] + b1[d0];
    hout[base + d1] = e1 * rstd2 * g1[d1] + b1[d1];
}

__global__ void addln1_kernel(const float* __restrict__ tmp,
                              const float* __restrict__ h,
                              const float* __restrict__ g, const float* __restrict__ b,
                              float* __restrict__ out) {
    __shared__ float red[32];
    const int r = blockIdx.x;
    const int d0 = threadIdx.x, d1 = threadIdx.x + 256;
    size_t base = (size_t)r * DD;

    float v0 = tmp[base + d0] + h[base + d0];
    float v1 = tmp[base + d1] + h[base + d1];

    float mean = blockReduceSum256(v0 + v1, red) * (1.f / DD);
    float e0 = v0 - mean, e1 = v1 - mean;
    float var = blockReduceSum256(e0 * e0 + e1 * e1, red) * (1.f / DD);
    float rstd = rsqrtf(var + EPS);

    out[base + d0] = e0 * rstd * g[d0] + b[d0];
    out[base + d1] = e1 * rstd * g[d1] + b[d1];
}

// ======================================================================
// launch
// ======================================================================
extern "C" void kernel_launch(void* const* d_in, const int* in_sizes, int n_in,
                              void* d_out, int out_size) {
    const float* x      = (const float*)d_in[0];
    const float* Wq     = (const float*)d_in[1];
    const float* bq     = (const float*)d_in[2];
    const float* Wk     = (const float*)d_in[3];
    const float* bk     = (const float*)d_in[4];
    const float* Wv     = (const float*)d_in[5];
    const float* bv     = (const float*)d_in[6];
    const float* Wo     = (const float*)d_in[7];
    const float* bo     = (const float*)d_in[8];
    const float* g_mha  = (const float*)d_in[9];
    const float* b_mha  = (const float*)d_in[10];
    const float* g_net1 = (const float*)d_in[11];
    const float* b_net1 = (const float*)d_in[12];
    const float* W1     = (const float*)d_in[13];
    const float* b1     = (const float*)d_in[14];
    const float* W2     = (const float*)d_in[15];
    const float* b2     = (const float*)d_in[16];
    const float* g_net2 = (const float*)d_in[17];
    const float* b_net2 = (const float*)d_in[18];

    float* qb;  cudaGetSymbolAddress((void**)&qb,  g_q);
    float* kb;  cudaGetSymbolAddress((void**)&kb,  g_k);
    float* vb;  cudaGetSymbolAddress((void**)&vb,  g_v);
    float* ctx; cudaGetSymbolAddress((void**)&ctx, g_ctx);
    float* tmp; cudaGetSymbolAddress((void**)&tmp, g_tmp);
    float* hb;  cudaGetSymbolAddress((void**)&hb,  g_h);
    float* hhb; cudaGetSymbolAddress((void**)&hhb, g_hh);
    __nv_bfloat16 *qhi, *qlo, *khi, *klo;
    cudaGetSymbolAddress((void**)&qhi, g_qhi);
    cudaGetSymbolAddress((void**)&qlo, g_qlo);
    cudaGetSymbolAddress((void**)&khi, g_khi);
    cudaGetSymbolAddress((void**)&klo, g_klo);

    const size_t OUT_ELEMS = (size_t)BB * SS * DD;
    float* outp = (float*)d_out;
    float* atnp = (float*)d_out + OUT_ELEMS;

    cudaFuncSetAttribute(score_hmma, cudaFuncAttributeMaxDynamicSharedMemorySize, SH_SMEM);

    dim3 gproj(DD / 128, MT / 128);
    sgemm_bias<<<gproj, 256>>>(x, Wq, bq, qb, MT, DD, DD);
    sgemm_bias<<<gproj, 256>>>(x, Wk, bk, kb, MT, DD, DD);
    sgemm_bias<<<gproj, 256>>>(x, Wv, bv, vb, MT, DD, DD);

    // split q (pre-scaled by 1/8) and k into bf16 hi/lo
    split_bf16<<<MT * DD / 1024, 256>>>(qb, qhi, qlo, 0.125f);
    split_bf16<<<MT * DD / 1024, 256>>>(kb, khi, klo, 1.0f);

    dim3 gscore(SS / 128, SS / 128, BB * HH);   // 16 x 16 x 32
    score_hmma<<<gscore, 256, SH_SMEM>>>(qhi, qlo, khi, klo, atnp);

    softmax_rows<<<BB * HH * SS, 256>>>(atnp);

    dim3 gctx(BB * HH, SS / 128);
    ctx_gemm<<<gctx, 256>>>(atnp, vb, ctx);

    sgemm_bias<<<gproj, 256>>>(ctx, Wo, bo, tmp, MT, DD, DD);

    addln2_kernel<<<MT, 256>>>(tmp, x, g_mha, b_mha, g_net1, b_net1, hb);

    ffn1_gemm<<<MT / 128, 256>>>(hb, W1, b1, hhb);

    sgemm_bias<<<gproj, 256>>>(hhb, W2, b2, tmp, MT, DD, FF);

    addln1_kernel<<<MT, 256>>>(tmp, hb, g_net2, b_net2, outp);
}

// round 11
// speedup vs baseline: 3.9301x; 1.5954x over previous
#include <cuda_runtime.h>
#include <cuda_bf16.h>
#include <math.h>
#include <cstdint>

// Problem constants
#define BB 4
#define SS 2048
#define DD 512
#define HH 8
#define KK 64
#define FF 64
#define MT (BB*SS)
#define EPS 1e-5f

// -------- scratch (no allocation allowed) --------
__device__ float g_q  [MT*DD];
__device__ float g_k  [MT*DD];
__device__ float g_v  [MT*DD];
__device__ float g_ctx[MT*DD];
__device__ float g_tmp[MT*DD];
__device__ float g_h  [MT*DD];
__device__ float g_hh [MT*FF];
__device__ __nv_bfloat16 g_qhi[MT*DD];
__device__ __nv_bfloat16 g_qlo[MT*DD];
__device__ __nv_bfloat16 g_khi[MT*DD];
__device__ __nv_bfloat16 g_klo[MT*DD];
// transposed+split weights: [N][K] bf16 hi/lo
__device__ __nv_bfloat16 g_wqt_h[DD*DD], g_wqt_l[DD*DD];
__device__ __nv_bfloat16 g_wkt_h[DD*DD], g_wkt_l[DD*DD];
__device__ __nv_bfloat16 g_wvt_h[DD*DD], g_wvt_l[DD*DD];
__device__ __nv_bfloat16 g_wot_h[DD*DD], g_wot_l[DD*DD];
__device__ __nv_bfloat16 g_w2t_h[DD*FF], g_w2t_l[DD*FF];
// V transposed+split: [bh][d=64][s=2048]
__device__ __nv_bfloat16 g_vt_h[BB*HH*KK*SS], g_vt_l[BB*HH*KK*SS];

// ======================================================================
// warp-level MMA helpers
// ======================================================================
__device__ __forceinline__ uint32_t smem_u32(const void* p) {
    uint32_t a;
    asm("{ .reg .u64 t; cvta.to.shared.u64 t, %1; cvt.u32.u64 %0, t; }"
        : "=r"(a) : "l"(p));
    return a;
}
__device__ __forceinline__ void ldsm_x4(uint32_t r[4], uint32_t addr) {
    asm volatile("ldmatrix.sync.aligned.m8n8.x4.shared.b16 {%0,%1,%2,%3}, [%4];"
        : "=r"(r[0]), "=r"(r[1]), "=r"(r[2]), "=r"(r[3]) : "r"(addr));
}
__device__ __forceinline__ void ldsm_x2(uint32_t r[2], uint32_t addr) {
    asm volatile("ldmatrix.sync.aligned.m8n8.x2.shared.b16 {%0,%1}, [%2];"
        : "=r"(r[0]), "=r"(r[1]) : "r"(addr));
}
__device__ __forceinline__ void mma_bf16(float d[4], const uint32_t a[4],
                                         const uint32_t b[2]) {
    asm volatile("mma.sync.aligned.m16n8k16.row.col.f32.bf16.bf16.f32 "
        "{%0,%1,%2,%3}, {%4,%5,%6,%7}, {%8,%9}, {%0,%1,%2,%3};"
        : "+f"(d[0]), "+f"(d[1]), "+f"(d[2]), "+f"(d[3])
        : "r"(a[0]), "r"(a[1]), "r"(a[2]), "r"(a[3]), "r"(b[0]), "r"(b[1]));
}
__device__ __forceinline__ void split2(float v, __nv_bfloat16& h, __nv_bfloat16& l) {
    h = __float2bfloat16(v);
    l = __float2bfloat16(v - __bfloat162float(h));
}

// ======================================================================
// weight split-transpose: W[K][N] fp32 -> Wt hi/lo [N][K] bf16
// ======================================================================
__global__ void __launch_bounds__(256)
split_wt(const float* __restrict__ W,
         __nv_bfloat16* __restrict__ th,
         __nv_bfloat16* __restrict__ tl,
         int Kd, int N) {
    __shared__ float tile[64][65];
    const int tid = threadIdx.x;
    const int k0 = blockIdx.x * 64, n0 = blockIdx.y * 64;
    #pragma unroll
    for (int i = 0; i < 16; i++) {
        int lin = tid + i * 256;
        int r = lin >> 6, c = lin & 63;
        tile[r][c] = W[(size_t)(k0 + r) * N + n0 + c];
    }
    __syncthreads();
    #pragma unroll
    for (int i = 0; i < 8; i++) {
        int lin = tid + i * 256;
        int n = lin >> 5, k2 = (lin & 31) * 2;
        float v0 = tile[k2][n], v1 = tile[k2 + 1][n];
        __nv_bfloat16 h0, l0, h1, l1;
        split2(v0, h0, l0); split2(v1, h1, l1);
        size_t o = (size_t)(n0 + n) * Kd + k0 + k2;
        *(__nv_bfloat162*)&th[o] = {h0, h1};
        *(__nv_bfloat162*)&tl[o] = {l0, l1};
    }
}

// ======================================================================
// V split-transpose: per (b,h): V[s][d] -> vt hi/lo [bh][d][s]
// ======================================================================
__global__ void __launch_bounds__(256)
v_split_t(const float* __restrict__ v,
          __nv_bfloat16* __restrict__ th,
          __nv_bfloat16* __restrict__ tl) {
    __shared__ float tile[64][65];
    const int tid = threadIdx.x;
    const int bh = blockIdx.x, b = bh >> 3, h = bh & 7;
    const int s0 = blockIdx.y * 64;
    #pragma unroll
    for (int i = 0; i < 16; i++) {
        int lin = tid + i * 256;
        int r = lin >> 6, c = lin & 63;   // r = s offset, c = d
        tile[r][c] = v[(size_t)(b * SS + s0 + r) * DD + h * KK + c];
    }
    __syncthreads();
    #pragma unroll
    for (int i = 0; i < 8; i++) {
        int lin = tid + i * 256;
        int d = lin >> 5, s2 = (lin & 31) * 2;
        float v0 = tile[s2][d], v1 = tile[s2 + 1][d];
        __nv_bfloat16 h0, l0, h1, l1;
        split2(v0, h0, l0); split2(v1, h1, l1);
        size_t o = ((size_t)bh * KK + d) * SS + s0 + s2;
        *(__nv_bfloat162*)&th[o] = {h0, h1};
        *(__nv_bfloat162*)&tl[o] = {l0, l1};
    }
}

// ======================================================================
// gemm_hmma: C[M,N] = A[M,Kd](fp32) @ Wt^T + bias, Wt hi/lo = [N][Kd] bf16.
// 3-term compensated: Ah*Bh + Ah*Bl + Al*Bh. CTA 128x128, 8 warps 2x4 (64x32).
// A converted to bf16 hi/lo in-kernel. smem stride 40 halves (80B).
// ======================================================================
__global__ void __launch_bounds__(256)
gemm_hmma(const float* __restrict__ A,
          const __nv_bfloat16* __restrict__ Bth,
          const __nv_bfloat16* __restrict__ Btl,
          const float* __restrict__ bias,
          float* __restrict__ C,
          int M, int N, int Kd) {
    __shared__ __nv_bfloat16 sAh[128 * 40], sAl[128 * 40];
    __shared__ __nv_bfloat16 sBh[128 * 40], sBl[128 * 40];

    const int tid = threadIdx.x, wid = tid >> 5, lane = tid & 31;
    const int m0 = blockIdx.y * 128, n0 = blockIdx.x * 128;
    const int wm = (wid >> 2) * 64, wn = (wid & 3) * 32;
    const int la16 = lane & 15;

    float acc[4][4][4];
    #pragma unroll
    for (int mt = 0; mt < 4; mt++)
        #pragma unroll
        for (int nt = 0; nt < 4; nt++)
            #pragma unroll
            for (int e = 0; e < 4; e++) acc[mt][nt][e] = 0.f;

    const uint32_t sAhB = smem_u32(sAh), sAlB = smem_u32(sAl);
    const uint32_t sBhB = smem_u32(sBh), sBlB = smem_u32(sBl);
    const uint32_t a_off = (uint32_t)((wm + la16) * 80 + (lane >> 4) * 16);
    const uint32_t b_off = (uint32_t)((wn + (la16 & 7)) * 80 + ((la16 >> 3) & 1) * 16);

    for (int kt = 0; kt < Kd; kt += 32) {
        // A: 128 rows x 32 k fp32 -> hi/lo
        #pragma unroll
        for (int i = 0; i < 4; i++) {
            int idx = tid + i * 256;
            int row = idx >> 3, c4 = (idx & 7) * 4;
            float4 av = *(const float4*)&A[(size_t)(m0 + row) * Kd + kt + c4];
            __nv_bfloat16 hx, lx, hy, ly, hz, lz, hw, lw;
            split2(av.x, hx, lx); split2(av.y, hy, ly);
            split2(av.z, hz, lz); split2(av.w, hw, lw);
            int so = row * 40 + c4;
            *(__nv_bfloat162*)&sAh[so]     = {hx, hy};
            *(__nv_bfloat162*)&sAh[so + 2] = {hz, hw};
            *(__nv_bfloat162*)&sAl[so]     = {lx, ly};
            *(__nv_bfloat162*)&sAl[so + 2] = {lz, lw};
        }
        // B: 128 rows x 32 halves (hi & lo)
        #pragma unroll
        for (int i = 0; i < 2; i++) {
            int idx = tid + i * 256;
            int row = idx >> 2, c8 = (idx & 3) * 8;
            size_t go = (size_t)(n0 + row) * Kd + kt + c8;
            *(uint4*)&sBh[row * 40 + c8] = *(const uint4*)&Bth[go];
            *(uint4*)&sBl[row * 40 + c8] = *(const uint4*)&Btl[go];
        }
        __syncthreads();

        #pragma unroll
        for (int ks = 0; ks < 2; ks++) {
            const uint32_t kbyte = ks * 32;
            uint32_t af[4][4], bh_[4][2], bl_[4][2];
            #pragma unroll
            for (int mt = 0; mt < 4; mt++)
                ldsm_x4(af[mt], sAhB + a_off + mt * 16 * 80 + kbyte);
            #pragma unroll
            for (int nt = 0; nt < 4; nt++) {
                ldsm_x2(bh_[nt], sBhB + b_off + nt * 8 * 80 + kbyte);
                ldsm_x2(bl_[nt], sBlB + b_off + nt * 8 * 80 + kbyte);
            }
            #pragma unroll
            for (int mt = 0; mt < 4; mt++)
                #pragma unroll
                for (int nt = 0; nt < 4; nt++) {
                    mma_bf16(acc[mt][nt], af[mt], bh_[nt]);
                    mma_bf16(acc[mt][nt], af[mt], bl_[nt]);
                }
            #pragma unroll
            for (int mt = 0; mt < 4; mt++)
                ldsm_x4(af[mt], sAlB + a_off + mt * 16 * 80 + kbyte);
            #pragma unroll
            for (int mt = 0; mt < 4; mt++)
                #pragma unroll
                for (int nt = 0; nt < 4; nt++)
                    mma_bf16(acc[mt][nt], af[mt], bh_[nt]);
        }
        __syncthreads();
    }

    const int rq = lane >> 2, cq = (lane & 3) * 2;
    #pragma unroll
    for (int mt = 0; mt < 4; mt++) {
        #pragma unroll
        for (int nt = 0; nt < 4; nt++) {
            int row = m0 + wm + mt * 16 + rq;
            int col = n0 + wn + nt * 8 + cq;
            float b0 = bias[col], b1 = bias[col + 1];
            *(float2*)&C[(size_t)row * N + col] =
                make_float2(acc[mt][nt][0] + b0, acc[mt][nt][1] + b1);
            *(float2*)&C[(size_t)(row + 8) * N + col] =
                make_float2(acc[mt][nt][2] + b0, acc[mt][nt][3] + b1);
        }
    }
}

// ======================================================================
// split into bf16 hi/lo (with scale folded in) — for q, k
// ======================================================================
__global__ void __launch_bounds__(256)
split_bf16(const float* __restrict__ src,
           __nv_bfloat16* __restrict__ hi,
           __nv_bfloat16* __restrict__ lo,
           float scale) {
    int i = (blockIdx.x * 256 + threadIdx.x) * 4;
    float4 v = *(const float4*)&src[i];
    v.x *= scale; v.y *= scale; v.z *= scale; v.w *= scale;
    __nv_bfloat16 hx, lx, hy, ly, hz, lz, hw, lw;
    split2(v.x, hx, lx); split2(v.y, hy, ly);
    split2(v.z, hz, lz); split2(v.w, hw, lw);
    *(__nv_bfloat162*)&hi[i]     = {hx, hy};
    *(__nv_bfloat162*)&hi[i + 2] = {hz, hw};
    *(__nv_bfloat162*)&lo[i]     = {lx, ly};
    *(__nv_bfloat162*)&lo[i + 2] = {lz, lw};
}

// ======================================================================
// score_hmma (unchanged from R9, passing)
// ======================================================================
#define RST 72
#define RSB 144
#define TILE_HALVES (128 * RST)
#define SH_SMEM (4 * TILE_HALVES * 2)

__global__ void __launch_bounds__(256)
score_hmma(const __nv_bfloat16* __restrict__ qhi,
           const __nv_bfloat16* __restrict__ qlo,
           const __nv_bfloat16* __restrict__ khi,
           const __nv_bfloat16* __restrict__ klo,
           float* __restrict__ atn) {
    extern __shared__ __nv_bfloat16 sh[];
    __nv_bfloat16* sQhi = sh;
    __nv_bfloat16* sQlo = sh + TILE_HALVES;
    __nv_bfloat16* sKhi = sh + 2 * TILE_HALVES;
    __nv_bfloat16* sKlo = sh + 3 * TILE_HALVES;

    const int tid  = threadIdx.x;
    const int wid  = tid >> 5, lane = tid & 31;
    const int bh   = blockIdx.z, b = bh >> 3, h = bh & 7;
    const int m0   = blockIdx.y * 128;
    const int n0   = blockIdx.x * 128;

    #pragma unroll
    for (int i = 0; i < 4; i++) {
        int idx = tid + i * 256;
        int row = idx >> 3, c8 = idx & 7;
        int soff = row * RST + c8 * 8;
        size_t qg = (size_t)(b * SS + m0 + row) * DD + h * KK + c8 * 8;
        size_t kg = (size_t)(b * SS + n0 + row) * DD + h * KK + c8 * 8;
        *(uint4*)&sQhi[soff] = *(const uint4*)&qhi[qg];
        *(uint4*)&sQlo[soff] = *(const uint4*)&qlo[qg];
        *(uint4*)&sKhi[soff] = *(const uint4*)&khi[kg];
        *(uint4*)&sKlo[soff] = *(const uint4*)&klo[kg];
    }
    __syncthreads();

    const int wr = wid >> 2, wc = wid & 3;
    const int wm = wr * 64, wn = wc * 32;

    float acc[4][4][4];
    #pragma unroll
    for (int mt = 0; mt < 4; mt++)
        #pragma unroll
        for (int nt = 0; nt < 4; nt++)
            #pragma unroll
            for (int e = 0; e < 4; e++) acc[mt][nt][e] = 0.f;

    const uint32_t qhiA = smem_u32(sQhi), qloA = smem_u32(sQlo);
    const uint32_t khiA = smem_u32(sKhi), kloA = smem_u32(sKlo);
    const int la16 = lane & 15;
    const uint32_t a_off = (uint32_t)((wm + la16) * RSB + (lane >> 4) * 16);
    const uint32_t b_off = (uint32_t)((wn + (la16 & 7)) * RSB + ((la16 >> 3) & 1) * 16);

    const uint32_t qbases[3] = {qhiA, qhiA, qloA};
    const uint32_t kbases[3] = {khiA, kloA, khiA};

    #pragma unroll
    for (int t = 0; t < 3; t++) {
        const uint32_t qb = qbases[t], kb = kbases[t];
        #pragma unroll
        for (int kkt = 0; kkt < 4; kkt++) {
            const uint32_t kbyte = kkt * 32;
            uint32_t afrag[4][4], bfrag[4][2];
            #pragma unroll
            for (int mt = 0; mt < 4; mt++)
                ldsm_x4(afrag[mt], qb + a_off + mt * 16 * RSB + kbyte);
            #pragma unroll
            for (int nt = 0; nt < 4; nt++)
                ldsm_x2(bfrag[nt], kb + b_off + nt * 8 * RSB + kbyte);
            #pragma unroll
            for (int mt = 0; mt < 4; mt++)
                #pragma unroll
                for (int nt = 0; nt < 4; nt++)
                    mma_bf16(acc[mt][nt], afrag[mt], bfrag[nt]);
        }
    }

    const size_t abase = (size_t)(h * BB + b) * SS * SS;
    const int rq = lane >> 2;
    const int cq = (lane & 3) * 2;
    #pragma unroll
    for (int mt = 0; mt < 4; mt++) {
        #pragma unroll
        for (int nt = 0; nt < 4; nt++) {
            size_t r0 = abase + (size_t)(m0 + wm + mt * 16 + rq) * SS + n0 + wn + nt * 8 + cq;
            *(float2*)&atn[r0]          = make_float2(acc[mt][nt][0], acc[mt][nt][1]);
            *(float2*)&atn[r0 + 8 * SS] = make_float2(acc[mt][nt][2], acc[mt][nt][3]);
        }
    }
}

// ======================================================================
// ctx_hmma: per (b,h): ctx[2048,64] = P @ V. P fp32 from atn, converted
// to bf16 hi/lo in-kernel; V pre-split/transposed. 3-term compensated.
// CTA: 128 q x 64 d, 8 warps 4x2 (32x32). k-chunk 64.
// ======================================================================
#define CP_OFF  0
#define CPL_OFF (128 * RST)
#define CVH_OFF (2 * 128 * RST)
#define CVL_OFF (2 * 128 * RST + 64 * RST)
#define CTX_SMEM ((2 * 128 * RST + 2 * 64 * RST) * 2)

__global__ void __launch_bounds__(256)
ctx_hmma(const float* __restrict__ P,
         const __nv_bfloat16* __restrict__ vth,
         const __nv_bfloat16* __restrict__ vtl,
         float* __restrict__ ctx) {
    extern __shared__ __nv_bfloat16 sh[];
    __nv_bfloat16* sPh = sh + CP_OFF;
    __nv_bfloat16* sPl = sh + CPL_OFF;
    __nv_bfloat16* sVh = sh + CVH_OFF;
    __nv_bfloat16* sVl = sh + CVL_OFF;

    const int tid = threadIdx.x, wid = tid >> 5, lane = tid & 31;
    const int bh = blockIdx.x, b = bh >> 3, h = bh & 7;
    const int q0 = blockIdx.y * 128;
    const size_t pbase = (size_t)(h * BB + b) * SS * SS;
    const size_t vbase = (size_t)bh * KK * SS;

    const int wm = (wid >> 1) * 32, wn = (wid & 1) * 32;
    const int la16 = lane & 15;

    float acc[2][4][4];
    #pragma unroll
    for (int mt = 0; mt < 2; mt++)
        #pragma unroll
        for (int nt = 0; nt < 4; nt++)
            #pragma unroll
            for (int e = 0; e < 4; e++) acc[mt][nt][e] = 0.f;

    const uint32_t sPhB = smem_u32(sPh), sPlB = smem_u32(sPl);
    const uint32_t sVhB = smem_u32(sVh), sVlB = smem_u32(sVl);
    const uint32_t a_off = (uint32_t)((wm + la16) * RSB + (lane >> 4) * 16);
    const uint32_t b_off = (uint32_t)((wn + (la16 & 7)) * RSB + ((la16 >> 3) & 1) * 16);

    for (int s0 = 0; s0 < SS; s0 += 64) {
        // P chunk: 128 q x 64 s fp32 -> hi/lo
        #pragma unroll
        for (int i = 0; i < 8; i++) {
            int idx = tid + i * 256;
            int row = idx >> 4, c4 = (idx & 15) * 4;
            float4 pv = *(const float4*)&P[pbase + (size_t)(q0 + row) * SS + s0 + c4];
            __nv_bfloat16 hx, lx, hy, ly, hz, lz, hw, lw;
            split2(pv.x, hx, lx); split2(pv.y, hy, ly);
            split2(pv.z, hz, lz); split2(pv.w, hw, lw);
            int so = row * RST + c4;
            *(__nv_bfloat162*)&sPh[so]     = {hx, hy};
            *(__nv_bfloat162*)&sPh[so + 2] = {hz, hw};
            *(__nv_bfloat162*)&sPl[so]     = {lx, ly};
            *(__nv_bfloat162*)&sPl[so + 2] = {lz, lw};
        }
        // V chunk: 64 d rows x 64 s halves
        #pragma unroll
        for (int i = 0; i < 2; i++) {
            int idx = tid + i * 256;
            int row = idx >> 3, c8 = (idx & 7) * 8;
            size_t go = vbase + (size_t)row * SS + s0 + c8;
            *(uint4*)&sVh[row * RST + c8] = *(const uint4*)&vth[go];
            *(uint4*)&sVl[row * RST + c8] = *(const uint4*)&vtl[go];
        }
        __syncthreads();

        #pragma unroll
        for (int ks = 0; ks < 4; ks++) {
            const uint32_t kbyte = ks * 32;
            uint32_t aph[2][4], apl[2][4], bvh[4][2], bvl[4][2];
            #pragma unroll
            for (int mt = 0; mt < 2; mt++) {
                ldsm_x4(aph[mt], sPhB + a_off + mt * 16 * RSB + kbyte);
                ldsm_x4(apl[mt], sPlB + a_off + mt * 16 * RSB + kbyte);
            }
            #pragma unroll
            for (int nt = 0; nt < 4; nt++) {
                ldsm_x2(bvh[nt], sVhB + b_off + nt * 8 * RSB + kbyte);
                ldsm_x2(bvl[nt], sVlB + b_off + nt * 8 * RSB + kbyte);
            }
            #pragma unroll
            for (int mt = 0; mt < 2; mt++)
                #pragma unroll
                for (int nt = 0; nt < 4; nt++) {
                    mma_bf16(acc[mt][nt], aph[mt], bvh[nt]);
                    mma_bf16(acc[mt][nt], apl[mt], bvh[nt]);
                    mma_bf16(acc[mt][nt], aph[mt], bvl[nt]);
                }
        }
        __syncthreads();
    }

    const int rq = lane >> 2, cq = (lane & 3) * 2;
    #pragma unroll
    for (int mt = 0; mt < 2; mt++) {
        #pragma unroll
        for (int nt = 0; nt < 4; nt++) {
            int row = b * SS + q0 + wm + mt * 16 + rq;
            int col = h * KK + wn + nt * 8 + cq;
            *(float2*)&ctx[(size_t)row * DD + col] =
                make_float2(acc[mt][nt][0], acc[mt][nt][1]);
            *(float2*)&ctx[(size_t)(row + 8) * DD + col] =
                make_float2(acc[mt][nt][2], acc[mt][nt][3]);
        }
    }
}

// ======================================================================
// fast exp (no MUFU) + reductions + softmax
// ======================================================================
__device__ __forceinline__ float fast_exp(float x) {
    x = fmaxf(x, -87.0f);
    float y0 = x * 1.4426950408889634f;
    float z  = y0 + 12582912.0f;
    float t  = z - 12582912.0f;
    float f  = y0 - t;
    int   n  = __float_as_int(z) - 0x4B400000;
    float p  = 0.0013333558f;
    p = fmaf(p, f, 0.0096181291f);
    p = fmaf(p, f, 0.0555041087f);
    p = fmaf(p, f, 0.2402265069f);
    p = fmaf(p, f, 0.6931471806f);
    p = fmaf(p, f, 1.0f);
    return p * __int_as_float((n + 127) << 23);
}

__device__ __forceinline__ float blockReduceSum256(float v, float* red) {
    #pragma unroll
    for (int o = 16; o; o >>= 1) v += __shfl_xor_sync(0xffffffff, v, o);
    int w = threadIdx.x >> 5;
    if ((threadIdx.x & 31) == 0) red[w] = v;
    __syncthreads();
    float r = 0.f;
    if (threadIdx.x < 32) {
        r = (threadIdx.x < 8) ? red[threadIdx.x] : 0.f;
        #pragma unroll
        for (int o = 4; o; o >>= 1) r += __shfl_xor_sync(0xffffffff, r, o);
        if (threadIdx.x == 0) red[0] = r;
    }
    __syncthreads();
    float out = red[0];
    __syncthreads();
    return out;
}

__device__ __forceinline__ float blockReduceMax256(float v, float* red) {
    #pragma unroll
    for (int o = 16; o; o >>= 1) v = fmaxf(v, __shfl_xor_sync(0xffffffff, v, o));
    int w = threadIdx.x >> 5;
    if ((threadIdx.x & 31) == 0) red[w] = v;
    __syncthreads();
    float r = -1e30f;
    if (threadIdx.x < 32) {
        r = (threadIdx.x < 8) ? red[threadIdx.x] : -1e30f;
        #pragma unroll
        for (int o = 4; o; o >>= 1) r = fmaxf(r, __shfl_xor_sync(0xffffffff, r, o));
        if (threadIdx.x == 0) red[0] = r;
    }
    __syncthreads();
    float out = red[0];
    __syncthreads();
    return out;
}

__global__ void __launch_bounds__(256)
softmax_rows(float* __restrict__ p) {
    __shared__ float red[32];
    size_t base = (size_t)blockIdx.x * SS + threadIdx.x * 8;

    float4 a = *(const float4*)&p[base];
    float4 c = *(const float4*)&p[base + 4];

    float mx = fmaxf(fmaxf(fmaxf(a.x, a.y), fmaxf(a.z, a.w)),
                     fmaxf(fmaxf(c.x, c.y), fmaxf(c.z, c.w)));
    mx = blockReduceMax256(mx, red);

    a.x = fast_exp(a.x - mx); a.y = fast_exp(a.y - mx);
    a.z = fast_exp(a.z - mx); a.w = fast_exp(a.w - mx);
    c.x = fast_exp(c.x - mx); c.y = fast_exp(c.y - mx);
    c.z = fast_exp(c.z - mx); c.w = fast_exp(c.w - mx);

    float sum = (a.x + a.y) + (a.z + a.w) + (c.x + c.y) + (c.z + c.w);
    sum = blockReduceSum256(sum, red);
    float inv = 1.f / sum;

    a.x *= inv; a.y *= inv; a.z *= inv; a.w *= inv;
    c.x *= inv; c.y *= inv; c.z *= inv; c.w *= inv;
    *(float4*)&p[base]     = a;
    *(float4*)&p[base + 4] = c;
}

// ======================================================================
// FFN1 GEMM + ReLU (FFMA, small)
// ======================================================================
__global__ void __launch_bounds__(256)
ffn1_gemm(const float* __restrict__ A,
          const float* __restrict__ W,
          const float* __restrict__ bias,
          float* __restrict__ C) {
    __shared__ __align__(16) float As[32 * 132];
    __shared__ __align__(16) float Ws[32 * 64];

    const int tid = threadIdx.x;
    const int m0  = blockIdx.x * 128;
    const int tq = tid >> 4;
    const int td = tid & 15;

    float acc[8][4];
    #pragma unroll
    for (int i = 0; i < 8; i++)
        #pragma unroll
        for (int j = 0; j < 4; j++) acc[i][j] = 0.f;

    for (int c = 0; c < DD; c += 32) {
        __syncthreads();
        #pragma unroll
        for (int i = 0; i < 4; i++) {
            int lin = tid + i * 256;
            int qr = lin >> 3, k4 = (lin & 7) * 4;
            float4 av = *(const float4*)&A[(size_t)(m0 + qr) * DD + c + k4];
            As[(k4 + 0) * 132 + qr] = av.x;
            As[(k4 + 1) * 132 + qr] = av.y;
            As[(k4 + 2) * 132 + qr] = av.z;
            As[(k4 + 3) * 132 + qr] = av.w;
        }
        #pragma unroll
        for (int i = 0; i < 2; i++) {
            int lin = tid + i * 256;
            int kr = lin >> 4, n4 = (lin & 15) * 4;
            *(float4*)&Ws[kr * 64 + n4] = *(const float4*)&W[(size_t)(c + kr) * FF + n4];
        }
        __syncthreads();

        #pragma unroll 8
        for (int s = 0; s < 32; s++) {
            float4 m0v = *(const float4*)&As[s * 132 + tq * 8];
            float4 m1v = *(const float4*)&As[s * 132 + tq * 8 + 4];
            float4 n0v = *(const float4*)&Ws[s * 64 + td * 4];
            float ma[8] = {m0v.x, m0v.y, m0v.z, m0v.w, m1v.x, m1v.y, m1v.z, m1v.w};
            float na[4] = {n0v.x, n0v.y, n0v.z, n0v.w};
            #pragma unroll
            for (int i = 0; i < 8; i++)
                #pragma unroll
                for (int j = 0; j < 4; j++)
                    acc[i][j] = fmaf(ma[i], na[j], acc[i][j]);
        }
    }

    float4 bv = *(const float4*)&bias[td * 4];
    float ba[4] = {bv.x, bv.y, bv.z, bv.w};
    #pragma unroll
    for (int i = 0; i < 8; i++) {
        float4 o = {fmaxf(acc[i][0] + ba[0], 0.f), fmaxf(acc[i][1] + ba[1], 0.f),
                    fmaxf(acc[i][2] + ba[2], 0.f), fmaxf(acc[i][3] + ba[3], 0.f)};
        *(float4*)&C[(size_t)(m0 + tq * 8 + i) * FF + td * 4] = o;
    }
}

// ======================================================================
// LN kernels
// ======================================================================
__global__ void addln2_kernel(const float* __restrict__ tmp,
                              const float* __restrict__ x,
                              const float* __restrict__ gm, const float* __restrict__ bm,
                              const float* __restrict__ g1, const float* __restrict__ b1,
                              float* __restrict__ hout) {
    __shared__ float red[32];
    const int r = blockIdx.x;
    const int d0 = threadIdx.x, d1 = threadIdx.x + 256;
    size_t base = (size_t)r * DD;

    float x0 = x[base + d0], x1 = x[base + d1];
    float p0 = tmp[base + d0] + x0;
    float p1 = tmp[base + d1] + x1;

    float mean = blockReduceSum256(p0 + p1, red) * (1.f / DD);
    float dv0 = p0 - mean, dv1 = p1 - mean;
    float var = blockReduceSum256(dv0 * dv0 + dv1 * dv1, red) * (1.f / DD);
    float rstd = rsqrtf(var + EPS);

    float m0 = dv0 * rstd * gm[d0] + bm[d0];
    float m1 = dv1 * rstd * gm[d1] + bm[d1];

    float t0 = m0 + x0, t1 = m1 + x1;
    float mean2 = blockReduceSum256(t0 + t1, red) * (1.f / DD);
    float e0 = t0 - mean2, e1 = t1 - mean2;
    float var2 = blockReduceSum256(e0 * e0 + e1 * e1, red) * (1.f / DD);
    float rstd2 = rsqrtf(var2 + EPS);

    hout[base + d0] = e0 * rstd2 * g1[d0] + b1[d0];
    hout[base + d1] = e1 * rstd2 * g1[d1] + b1[d1];
}

__global__ void addln1_kernel(const float* __restrict__ tmp,
                              const float* __restrict__ h,
                              const float* __restrict__ g, const float* __restrict__ b,
                              float* __restrict__ out) {
    __shared__ float red[32];
    const int r = blockIdx.x;
    const int d0 = threadIdx.x, d1 = threadIdx.x + 256;
    size_t base = (size_t)r * DD;

    float v0 = tmp[base + d0] + h[base + d0];
    float v1 = tmp[base + d1] + h[base + d1];

    float mean = blockReduceSum256(v0 + v1, red) * (1.f / DD);
    float e0 = v0 - mean, e1 = v1 - mean;
    float var = blockReduceSum256(e0 * e0 + e1 * e1, red) * (1.f / DD);
    float rstd = rsqrtf(var + EPS);

    out[base + d0] = e0 * rstd * g[d0] + b[d0];
    out[base + d1] = e1 * rstd * g[d1] + b[d1];
}

// ======================================================================
// launch
// ======================================================================
extern "C" void kernel_launch(void* const* d_in, const int* in_sizes, int n_in,
                              void* d_out, int out_size) {
    const float* x      = (const float*)d_in[0];
    const float* Wq     = (const float*)d_in[1];
    const float* bq     = (const float*)d_in[2];
    const float* Wk     = (const float*)d_in[3];
    const float* bk     = (const float*)d_in[4];
    const float* Wv     = (const float*)d_in[5];
    const float* bv     = (const float*)d_in[6];
    const float* Wo     = (const float*)d_in[7];
    const float* bo     = (const float*)d_in[8];
    const float* g_mha  = (const float*)d_in[9];
    const float* b_mha  = (const float*)d_in[10];
    const float* g_net1 = (const float*)d_in[11];
    const float* b_net1 = (const float*)d_in[12];
    const float* W1     = (const float*)d_in[13];
    const float* b1     = (const float*)d_in[14];
    const float* W2     = (const float*)d_in[15];
    const float* b2     = (const float*)d_in[16];
    const float* g_net2 = (const float*)d_in[17];
    const float* b_net2 = (const float*)d_in[18];

    float* qb;  cudaGetSymbolAddress((void**)&qb,  g_q);
    float* kb;  cudaGetSymbolAddress((void**)&kb,  g_k);
    float* vb;  cudaGetSymbolAddress((void**)&vb,  g_v);
    float* ctx; cudaGetSymbolAddress((void**)&ctx, g_ctx);
    float* tmp; cudaGetSymbolAddress((void**)&tmp, g_tmp);
    float* hb;  cudaGetSymbolAddress((void**)&hb,  g_h);
    float* hhb; cudaGetSymbolAddress((void**)&hhb, g_hh);
    __nv_bfloat16 *qhi, *qlo, *khi, *klo;
    cudaGetSymbolAddress((void**)&qhi, g_qhi);
    cudaGetSymbolAddress((void**)&qlo, g_qlo);
    cudaGetSymbolAddress((void**)&khi, g_khi);
    cudaGetSymbolAddress((void**)&klo, g_klo);
    __nv_bfloat16 *wqt_h, *wqt_l, *wkt_h, *wkt_l, *wvt_h, *wvt_l, *wot_h, *wot_l;
    __nv_bfloat16 *w2t_h, *w2t_l, *vt_h, *vt_l;
    cudaGetSymbolAddress((void**)&wqt_h, g_wqt_h);
    cudaGetSymbolAddress((void**)&wqt_l, g_wqt_l);
    cudaGetSymbolAddress((void**)&wkt_h, g_wkt_h);
    cudaGetSymbolAddress((void**)&wkt_l, g_wkt_l);
    cudaGetSymbolAddress((void**)&wvt_h, g_wvt_h);
    cudaGetSymbolAddress((void**)&wvt_l, g_wvt_l);
    cudaGetSymbolAddress((void**)&wot_h, g_wot_h);
    cudaGetSymbolAddress((void**)&wot_l, g_wot_l);
    cudaGetSymbolAddress((void**)&w2t_h, g_w2t_h);
    cudaGetSymbolAddress((void**)&w2t_l, g_w2t_l);
    cudaGetSymbolAddress((void**)&vt_h,  g_vt_h);
    cudaGetSymbolAddress((void**)&vt_l,  g_vt_l);

    const size_t OUT_ELEMS = (size_t)BB * SS * DD;
    float* outp = (float*)d_out;
    float* atnp = (float*)d_out + OUT_ELEMS;

    cudaFuncSetAttribute(score_hmma, cudaFuncAttributeMaxDynamicSharedMemorySize, SH_SMEM);
    cudaFuncSetAttribute(ctx_hmma, cudaFuncAttributeMaxDynamicSharedMemorySize, CTX_SMEM);

    // weight split-transpose
    dim3 gswt(DD / 64, DD / 64);
    split_wt<<<gswt, 256>>>(Wq, wqt_h, wqt_l, DD, DD);
    split_wt<<<gswt, 256>>>(Wk, wkt_h, wkt_l, DD, DD);
    split_wt<<<gswt, 256>>>(Wv, wvt_h, wvt_l, DD, DD);
    split_wt<<<gswt, 256>>>(Wo, wot_h, wot_l, DD, DD);
    split_wt<<<dim3(FF / 64, DD / 64), 256>>>(W2, w2t_h, w2t_l, FF, DD);

    // projections (HMMA)
    dim3 gproj(DD / 128, MT / 128);
    gemm_hmma<<<gproj, 256>>>(x, wqt_h, wqt_l, bq, qb, MT, DD, DD);
    gemm_hmma<<<gproj, 256>>>(x, wkt_h, wkt_l, bk, kb, MT, DD, DD);
    gemm_hmma<<<gproj, 256>>>(x, wvt_h, wvt_l, bv, vb, MT, DD, DD);

    split_bf16<<<MT * DD / 1024, 256>>>(qb, qhi, qlo, 0.125f);
    split_bf16<<<MT * DD / 1024, 256>>>(kb, khi, klo, 1.0f);
    v_split_t<<<dim3(BB * HH, SS / 64), 256>>>(vb, vt_h, vt_l);

    dim3 gscore(SS / 128, SS / 128, BB * HH);
    score_hmma<<<gscore, 256, SH_SMEM>>>(qhi, qlo, khi, klo, atnp);

    softmax_rows<<<BB * HH * SS, 256>>>(atnp);

    dim3 gctx(BB * HH, SS / 128);
    ctx_hmma<<<gctx, 256, CTX_SMEM>>>(atnp, vt_h, vt_l, ctx);

    gemm_hmma<<<gproj, 256>>>(ctx, wot_h, wot_l, bo, tmp, MT, DD, DD);

    addln2_kernel<<<MT, 256>>>(tmp, x, g_mha, b_mha, g_net1, b_net1, hb);

    ffn1_gemm<<<MT / 128, 256>>>(hb, W1, b1, hhb);

    gemm_hmma<<<gproj, 256>>>(hhb, w2t_h, w2t_l, b2, tmp, MT, DD, FF);

    addln1_kernel<<<MT, 256>>>(tmp, hb, g_net2, b_net2, outp);
}